// round 14
// baseline (speedup 1.0000x reference)
#include <cuda_runtime.h>
#include <cuda_bf16.h>
#include <cuda_fp16.h>
#include <cstdint>
#include <math.h>

#define Tn   128
#define Bn   64
#define Hn   1024
#define NUn  256
#define Vn   8000
#define FH   4096
#define NBLK 96
#define APLANE 4194304    // 8192*512: one plane of a K=256 A-frag image
#define HPLANE 16777216   // 8192*2048: one plane of the K=1024 H1 A-frag image

// ------------------------------ device scratch ----------------------------
__device__ float g_GX0[Tn * Bn * FH];     // BN(x@Wx0) with gx0 folded

// scan weights: A-fragment images, SINGLE fp16 plane per CTA slice
__device__ __align__(16) unsigned char g_W0f [32 * 262144];
__device__ __align__(16) unsigned char g_W1xf[64 * 131072];
__device__ __align__(16) unsigned char g_W1hf[64 * 131072];
// h states as B-fragment images, single fp16 plane: [parity][128KB]
__device__ __align__(16) unsigned char g_h0B[2][131072];
__device__ __align__(16) unsigned char g_h1B[2][131072];
// A-frag images (bf16 hi|lo)
__device__ __align__(16) unsigned char g_Xf[2 * APLANE];   // X, K=256
__device__ __align__(16) unsigned char g_Yf[2 * APLANE];   // Y, K=256
__device__ __align__(16) unsigned char g_Hf[2 * HPLANE];   // H1, K=1024
// B-frag images (bf16 hi|lo)
__device__ __align__(16) unsigned char g_Wx0B[2 * 4096 * 512];
__device__ __align__(16) unsigned char g_swB [2 * 8000 * 512];
__device__ __align__(16) unsigned char g_WpB [2 * 4 * 131072];

__device__ unsigned g_barCnt;
__device__ volatile unsigned g_barGen;

__device__ __forceinline__ float sigm(float x) { return __fdividef(1.f, 1.f + __expf(-x)); }

#define MMAB(c, a, b) \
    asm volatile("mma.sync.aligned.m16n8k16.row.col.f32.bf16.bf16.f32 " \
        "{%0,%1,%2,%3},{%4,%5,%6,%7},{%8,%9},{%0,%1,%2,%3};" \
        : "+f"((c)[0]), "+f"((c)[1]), "+f"((c)[2]), "+f"((c)[3]) \
        : "r"((a).x), "r"((a).y), "r"((a).z), "r"((a).w), "r"((b).x), "r"((b).y))
#define MMAH(c, a, b) \
    asm volatile("mma.sync.aligned.m16n8k16.row.col.f32.f16.f16.f32 " \
        "{%0,%1,%2,%3},{%4,%5,%6,%7},{%8,%9},{%0,%1,%2,%3};" \
        : "+f"((c)[0]), "+f"((c)[1]), "+f"((c)[2]), "+f"((c)[3]) \
        : "r"((a).x), "r"((a).y), "r"((a).z), "r"((a).w), "r"((b).x), "r"((b).y))

__device__ __forceinline__ uint32_t smem_u32(const void* p) {
    uint32_t a;
    asm("{ .reg .u64 t; cvta.to.shared.u64 t, %1; cvt.u32.u64 %0, t; }" : "=r"(a) : "l"(p));
    return a;
}
__device__ __forceinline__ void cpa16(uint32_t dst, const void* src) {
    asm volatile("cp.async.cg.shared.global [%0], [%1], 16;" :: "r"(dst), "l"(src) : "memory");
}
#define CP_COMMIT() asm volatile("cp.async.commit_group;" ::: "memory")
#define CP_WAIT(n)  asm volatile("cp.async.wait_group %0;" :: "n"(n) : "memory")

__device__ __forceinline__ void bulk_g2s(uint32_t dst, const void* src, uint32_t bytes, uint32_t mbar) {
    asm volatile(
        "cp.async.bulk.shared::cluster.global.mbarrier::complete_tx::bytes [%0], [%1], %2, [%3];"
        :: "r"(dst), "l"(src), "r"(bytes), "r"(mbar) : "memory");
}
#define MBAR_INIT(a, n) \
    asm volatile("mbarrier.init.shared.b64 [%0], %1;" :: "r"(a), "r"((uint32_t)(n)) : "memory")
#define MBAR_EXPECT(a, n) \
    asm volatile("mbarrier.arrive.expect_tx.shared.b64 _, [%0], %1;" :: "r"(a), "r"((uint32_t)(n)) : "memory")
#define MBAR_WAIT(a, ph) do {                                                  \
    uint32_t _m = (a), _p = (ph), _d;                                          \
    asm volatile("{\n\t.reg .pred p;\n\t"                                      \
        "mbarrier.try_wait.parity.acquire.cta.shared::cta.b64 p, [%1], %2;\n\t"\
        "selp.b32 %0, 1, 0, p;\n\t}"                                           \
        : "=r"(_d) : "r"(_m), "r"(_p) : "memory");                             \
    if (!_d) {                                                                 \
        asm volatile("{\n\t.reg .pred P1;\n\t"                                 \
            "W_%=:\n\t"                                                        \
            "mbarrier.try_wait.parity.acquire.cta.shared::cta.b64 P1, [%0], %1, 0x989680;\n\t" \
            "@P1 bra.uni D_%=;\n\tbra.uni W_%=;\n\tD_%=:\n\t}"                 \
            :: "r"(_m), "r"(_p) : "memory");                                   \
    }                                                                          \
} while (0)

__device__ __forceinline__ void grid_bar() {
    __syncthreads();
    if (threadIdx.x == 0) {
        unsigned gen = g_barGen;
        __threadfence();
        if (atomicAdd(&g_barCnt, 1u) == NBLK - 1) {
            g_barCnt = 0;
            __threadfence();
            g_barGen = gen + 1;
        } else {
            while (g_barGen == gen) { __nanosleep(64); }
        }
        __threadfence();
    }
    __syncthreads();
}

// A-fragment offset, K=256 image
__device__ __forceinline__ size_t afrag_off(int m, int k) {
    int mt = m >> 4, mi = m & 15, kt = k >> 4, ki = k & 15;
    int lane = (mi & 7) * 4 + ((ki & 7) >> 1);
    int reg  = (mi >> 3) + ((ki >> 3) << 1);
    return ((size_t)(mt * 16 + kt) << 9) + lane * 16 + (reg << 2) + ((ki & 1) << 1);
}
// A-fragment offset, K=1024 image
__device__ __forceinline__ size_t afrag_off1k(int m, int k) {
    int mt = m >> 4, mi = m & 15, kt = k >> 4, ki = k & 15;
    int lane = (mi & 7) * 4 + ((ki & 7) >> 1);
    int reg  = (mi >> 3) + ((ki >> 3) << 1);
    return ((size_t)(mt * 64 + kt) << 9) + lane * 16 + (reg << 2) + ((ki & 1) << 1);
}
// B-fragment offset, K=256 image (ntile-major)
__device__ __forceinline__ size_t bfrag_off(int k, int n) {
    int nt = n >> 3, ni = n & 7, kt = k >> 4, ki = k & 15;
    int ln = ni * 4 + ((ki & 7) >> 1);
    return ((size_t)(nt * 16 + kt) << 8) + ln * 8 + ((ki >> 3) << 2) + ((ki & 1) << 1);
}

// write one h value into the scan B-frag plane (kt-major tiles, K=1024), fp16
__device__ __forceinline__ void write_hfrag(unsigned char* hb, int b, int hc, float h) {
    int kt = hc >> 4, nt = b >> 3, ki = hc & 15, ni = b & 7;
    int ln = ni * 4 + ((ki & 7) >> 1);
    int off = ((kt * 8 + nt) << 8) + ln * 8 + ((ki >> 3) << 2) + ((ki & 1) << 1);
    *(__half*)(hb + off) = __float2half(h);
}

// ------------------------------ embedding + state init --------------------
__global__ void k_embed(const int* __restrict__ inp, const float* __restrict__ emb) {
    int row = blockIdx.x;                 // t*64 + b
    int u = threadIdx.x;
    int i = blockIdx.x * 256 + threadIdx.x;
    if (i < 65536) ((uint32_t*)g_h0B)[i] = 0u;
    else if (i < 131072) ((uint32_t*)g_h1B)[i - 65536] = 0u;
    int t = row >> 6, b = row & 63;
    float v = emb[(size_t)inp[b * Tn + t] * NUn + u];
    __nv_bfloat16 hi = __float2bfloat16(v);
    __nv_bfloat16 lo = __float2bfloat16(v - __bfloat162float(hi));
    size_t off = afrag_off(row, u);
    *(__nv_bfloat16*)(g_Xf + off) = hi;
    *(__nv_bfloat16*)(g_Xf + APLANE + off) = lo;
}

// ------------------------------ weights -> B-frags (merged, bf16) ---------
__global__ void k_prepB(const float* __restrict__ Wx0, const float* __restrict__ sw) {
    int idx = blockIdx.x * 256 + threadIdx.x;
    const float* W; unsigned char* dst; int N; int local;
    if (idx < NUn * FH) { W = Wx0; dst = g_Wx0B; N = FH; local = idx; }
    else { W = sw; dst = g_swB; N = Vn; local = idx - NUn * FH; }
    int k = local / N, n = local - k * N;
    float v = W[local];
    __nv_bfloat16 hi = __float2bfloat16(v);
    __nv_bfloat16 lo = __float2bfloat16(v - __bfloat162float(hi));
    size_t off = bfrag_off(k, n);
    *(__nv_bfloat16*)(dst + off) = hi;
    *(__nv_bfloat16*)(dst + (size_t)N * 512 + off) = lo;
}

// ------------------------------ Wp -> B-frags (K=1024, chunk-contiguous) --
__global__ void k_prepWp(const float* __restrict__ Wp) {
    int idx = blockIdx.x * 256 + threadIdx.x;   // k*256 + n
    int k = idx >> 8, n = idx & 255;
    float v = Wp[idx];
    __nv_bfloat16 hi = __float2bfloat16(v);
    __nv_bfloat16 lo = __float2bfloat16(v - __bfloat162float(hi));
    int nb = n >> 6, ntl = (n >> 3) & 7, ni = n & 7;
    int kt = k >> 4, ki = k & 15;
    int ln = ni * 4 + ((ki & 7) >> 1);
    size_t off = (size_t)nb * 131072 + ((size_t)(kt * 8 + ntl) << 8)
               + ln * 8 + ((ki >> 3) << 2) + ((ki & 1) << 1);
    *(__nv_bfloat16*)(g_WpB + off) = hi;
    *(__nv_bfloat16*)(g_WpB + 524288 + off) = lo;
}

// ------------------------------ scan weight prep (single fp16) ------------
__global__ void k_prepw(const float* __restrict__ Wh0, const float* __restrict__ Wx1,
                        const float* __restrict__ Wh1) {
    int which = blockIdx.y;
    const float* W = which == 0 ? Wh0 : (which == 1 ? Wx1 : Wh1);
    int idx = blockIdx.x * 256 + threadIdx.x;   // k*4096 + gcol
    int k = idx >> 12, gcol = idx & 4095;
    __half hv = __float2half(W[idx]);
    int g = gcol >> 10, hc = gcol & 1023;
    unsigned char* base;
    int MT, m;
    if (which == 0) {
        int c = hc >> 5; m = g * 32 + (hc & 31); MT = 8;
        base = g_W0f + (size_t)c * 262144;
    } else {
        int c = hc >> 4; m = g * 16 + (hc & 15); MT = 4;
        base = (which == 1 ? g_W1xf : g_W1hf) + (size_t)c * 131072;
    }
    int kt = k >> 4, ki = k & 15, mt = m >> 4, mi = m & 15;
    int lane = (mi & 7) * 4 + ((ki & 7) >> 1);
    int reg  = (mi >> 3) + ((ki >> 3) << 1);
    int off  = ((kt * MT + mt) << 9) + lane * 16 + (reg << 2) + ((ki & 1) << 1);
    *(__half*)(base + off) = hv;
}

// ------------------------------ GX0 MMA with fused per-timestep BN --------
__global__ void __launch_bounds__(256) k_gemm_gx0(
        const unsigned char* __restrict__ Af, const unsigned char* __restrict__ Bf,
        const float* __restrict__ gx0) {
    extern __shared__ unsigned char sb[];
    const int tid = threadIdx.x, w = tid >> 5, lane = tid & 31;
    const int nb = blockIdx.x, mb = blockIdx.y;
    {
        int p = tid >> 7, o = (tid & 127) * 16;
        const unsigned char* src = Bf + (size_t)p * ((size_t)FH * 512) + (size_t)nb * 32768 + o;
        uint32_t dst = smem_u32(sb + p * 32768 + o);
#pragma unroll
        for (int i = 0; i < 16; i++) cpa16(dst + i * 2048, src + i * 2048);
        CP_COMMIT(); CP_WAIT(0);
    }
    __syncthreads();
    const size_t abase = ((size_t)(mb * 8 + w) << 13) + lane * 16;
    uint4 ahc = *(const uint4*)(Af + abase);
    uint4 alc = *(const uint4*)(Af + APLANE + abase);
    float acc[8][4] = {};
#pragma unroll
    for (int kt = 0; kt < 16; kt++) {
        uint4 ahn, aln;
        if (kt < 15) {
            ahn = *(const uint4*)(Af + abase + (kt + 1) * 512);
            aln = *(const uint4*)(Af + APLANE + abase + (kt + 1) * 512);
        }
        uint2 bh[8], bl[8];
#pragma unroll
        for (int j = 0; j < 8; j++) {
            bh[j] = *(const uint2*)(sb + (j * 16 + kt) * 256 + lane * 8);
            bl[j] = *(const uint2*)(sb + 32768 + (j * 16 + kt) * 256 + lane * 8);
        }
#pragma unroll
        for (int j = 0; j < 8; j++) MMAB(acc[j], ahc, bh[j]);
#pragma unroll
        for (int j = 0; j < 8; j++) MMAB(acc[j], alc, bh[j]);
#pragma unroll
        for (int j = 0; j < 8; j++) MMAB(acc[j], ahc, bl[j]);
        ahc = ahn; alc = aln;
    }
    __syncthreads();
    float (*Cs)[65] = (float(*)[65])sb;
    float* mS = (float*)(sb + 33280);
    float* sS = (float*)(sb + 33792);
    int r0 = w * 16 + (lane >> 2);
#pragma unroll
    for (int j = 0; j < 8; j++) {
        int cl = j * 8 + (lane & 3) * 2;
        Cs[r0][cl] = acc[j][0]; Cs[r0][cl + 1] = acc[j][1];
        Cs[r0 + 8][cl] = acc[j][2]; Cs[r0 + 8][cl + 1] = acc[j][3];
    }
    __syncthreads();
    if (tid < 128) {
        int half = tid >> 6, col = tid & 63;
        float s = 0.f, s2 = 0.f;
#pragma unroll
        for (int b = 0; b < 64; b++) {
            float v = Cs[half * 64 + b][col];
            s += v; s2 += v * v;
        }
        float m = s * (1.f / 64.f);
        float var = fmaxf(s2 * (1.f / 64.f) - m * m, 0.f);
        mS[tid] = m;
        sS[tid] = gx0[nb * 64 + col] * rsqrtf(var + 1e-5f);
    }
    __syncthreads();
    {
        int col = tid & 63, seg = tid >> 6;
#pragma unroll
        for (int i = 0; i < 32; i++) {
            int rr = seg * 32 + i;
            int sidx = (rr >> 6) * 64 + col;
            g_GX0[(size_t)(mb * 128 + rr) * FH + nb * 64 + col] =
                sS[sidx] * (Cs[rr][col] - mS[sidx]);
        }
    }
}

// ------------------------------ logits MMA GEMM, K=256 --------------------
__global__ void __launch_bounds__(256) k_gemm_mma(
        const unsigned char* __restrict__ Af, const unsigned char* __restrict__ Bf,
        const float* __restrict__ bias, float* __restrict__ C, int N) {
    extern __shared__ unsigned char sb[];
    const int tid = threadIdx.x, w = tid >> 5, lane = tid & 31;
    const int nb = blockIdx.x, mb = blockIdx.y;
    {
        int p = tid >> 7, o = (tid & 127) * 16;
        const unsigned char* src = Bf + (size_t)p * ((size_t)N * 512) + (size_t)nb * 32768 + o;
        uint32_t dst = smem_u32(sb + p * 32768 + o);
#pragma unroll
        for (int i = 0; i < 16; i++) cpa16(dst + i * 2048, src + i * 2048);
        CP_COMMIT(); CP_WAIT(0);
    }
    __syncthreads();
    const size_t abase = ((size_t)(mb * 8 + w) << 13) + lane * 16;
    uint4 ahc = *(const uint4*)(Af + abase);
    uint4 alc = *(const uint4*)(Af + APLANE + abase);
    float acc[8][4] = {};
#pragma unroll
    for (int kt = 0; kt < 16; kt++) {
        uint4 ahn, aln;
        if (kt < 15) {
            ahn = *(const uint4*)(Af + abase + (kt + 1) * 512);
            aln = *(const uint4*)(Af + APLANE + abase + (kt + 1) * 512);
        }
        uint2 bh[8], bl[8];
#pragma unroll
        for (int j = 0; j < 8; j++) {
            bh[j] = *(const uint2*)(sb + (j * 16 + kt) * 256 + lane * 8);
            bl[j] = *(const uint2*)(sb + 32768 + (j * 16 + kt) * 256 + lane * 8);
        }
#pragma unroll
        for (int j = 0; j < 8; j++) MMAB(acc[j], ahc, bh[j]);
#pragma unroll
        for (int j = 0; j < 8; j++) MMAB(acc[j], alc, bh[j]);
#pragma unroll
        for (int j = 0; j < 8; j++) MMAB(acc[j], ahc, bl[j]);
        ahc = ahn; alc = aln;
    }
    int r0 = mb * 128 + w * 16 + (lane >> 2);
#pragma unroll
    for (int j = 0; j < 8; j++) {
        int col = nb * 64 + j * 8 + (lane & 3) * 2;
        float b0v = bias ? bias[col] : 0.f;
        float b1v = bias ? bias[col + 1] : 0.f;
        *(float2*)(C + (size_t)r0 * N + col) = make_float2(acc[j][0] + b0v, acc[j][1] + b1v);
        *(float2*)(C + (size_t)(r0 + 8) * N + col) = make_float2(acc[j][2] + b0v, acc[j][3] + b1v);
    }
}

// ------------------------------ Wp MMA GEMM, K=1024 -----------------------
__global__ void __launch_bounds__(256) k_gemm_wp(const float* __restrict__ bp) {
    extern __shared__ unsigned char sb[];
    __shared__ __align__(8) unsigned long long mbar[2];
    const int tid = threadIdx.x, w = tid >> 5, lane = tid & 31;
    const int nb = blockIdx.x, mb = blockIdx.y;
    const uint32_t mb0 = smem_u32(&mbar[0]), mb1 = smem_u32(&mbar[1]);
    if (tid == 0) { MBAR_INIT(mb0, 1); MBAR_INIT(mb1, 1); }
    __syncthreads();
    const unsigned char* Bbase = g_WpB + (size_t)nb * 131072;
    if (tid == 0) {
#pragma unroll
        for (int k0 = 0; k0 < 2; k0++) {
            uint32_t mbk = k0 ? mb1 : mb0;
            uint32_t slot = smem_u32(sb + k0 * 65536);
            MBAR_EXPECT(mbk, 65536);
            bulk_g2s(slot, Bbase + k0 * 32768, 32768, mbk);
            bulk_g2s(slot + 32768, Bbase + 524288 + k0 * 32768, 32768, mbk);
        }
    }
    const size_t abase = ((size_t)(mb * 8 + w) << 15) + lane * 16;
    int ph0 = 0, ph1 = 0;
    uint4 ahc = *(const uint4*)(g_Hf + abase);
    uint4 alc = *(const uint4*)(g_Hf + HPLANE + abase);
    float acc[8][4] = {};
    for (int kt = 0; kt < 64; kt++) {
        int kc = kt >> 4;
        if ((kt & 15) == 0) {
            if (kc & 1) { MBAR_WAIT(mb1, (uint32_t)(ph1 & 1)); ph1++; }
            else        { MBAR_WAIT(mb0, (uint32_t)(ph0 & 1)); ph0++; }
        }
        uint4 ahn, aln;
        if (kt < 63) {
            ahn = *(const uint4*)(g_Hf + abase + ((size_t)(kt + 1) << 9));
            aln = *(const uint4*)(g_Hf + HPLANE + abase + ((size_t)(kt + 1) << 9));
        }
        const unsigned char* bb = sb + (kc & 1) * 65536 + ((kt & 15) << 11);
        uint2 bh[8], bl[8];
#pragma unroll
        for (int j = 0; j < 8; j++) {
            bh[j] = *(const uint2*)(bb + (j << 8) + lane * 8);
            bl[j] = *(const uint2*)(bb + 32768 + (j << 8) + lane * 8);
        }
#pragma unroll
        for (int j = 0; j < 8; j++) MMAB(acc[j], ahc, bh[j]);
#pragma unroll
        for (int j = 0; j < 8; j++) MMAB(acc[j], alc, bh[j]);
#pragma unroll
        for (int j = 0; j < 8; j++) MMAB(acc[j], ahc, bl[j]);
        if ((kt & 15) == 15 && kc < 2) {
            __syncthreads();
            if (tid == 0) {
                uint32_t mbk = (kc & 1) ? mb1 : mb0;
                uint32_t slot = smem_u32(sb + (kc & 1) * 65536);
                MBAR_EXPECT(mbk, 65536);
                bulk_g2s(slot, Bbase + (kc + 2) * 32768, 32768, mbk);
                bulk_g2s(slot + 32768, Bbase + 524288 + (kc + 2) * 32768, 32768, mbk);
            }
        }
        ahc = ahn; alc = aln;
    }
    int r0 = mb * 128 + w * 16 + (lane >> 2);
#pragma unroll
    for (int j = 0; j < 8; j++) {
        int col = nb * 64 + j * 8 + (lane & 3) * 2;
        float y[4] = { acc[j][0] + bp[col], acc[j][1] + bp[col + 1],
                       acc[j][2] + bp[col], acc[j][3] + bp[col + 1] };
        int rows[4] = { r0, r0, r0 + 8, r0 + 8 };
        int cols[4] = { col, col + 1, col, col + 1 };
#pragma unroll
        for (int q = 0; q < 4; q++) {
            __nv_bfloat16 hi = __float2bfloat16(y[q]);
            __nv_bfloat16 lo = __float2bfloat16(y[q] - __bfloat162float(hi));
            size_t off = afrag_off(rows[q], cols[q]);
            *(__nv_bfloat16*)(g_Yf + off) = hi;
            *(__nv_bfloat16*)(g_Yf + APLANE + off) = lo;
        }
    }
}

// ------------------------------ persistent scan (fp16, deep pipeline) -----
__global__ void __launch_bounds__(512) k_scan(
        const float* __restrict__ b0,  const float* __restrict__ gh0,
        const float* __restrict__ gc0, const float* __restrict__ bc0,
        const float* __restrict__ b1,  const float* __restrict__ gx1,
        const float* __restrict__ gh1, const float* __restrict__ gc1,
        const float* __restrict__ bc1) {
    extern __shared__ __align__(16) unsigned char sm[];
    float (*Cs)[65] = (float(*)[65])sm;            // raw gate pre-acts (aliases staging)
    float* psA  = (float*)(sm + 131072);           // 512
    float* ps2A = psA + 512;                       // 512
    float* mcA  = ps2A + 512;                      // 32
    float* rsA  = mcA + 32;                        // 32
    float* prS  = rsA + 32;                        // 256
    float* pqS  = prS + 256;                       // 256
    float* mS   = pqS + 256;                       // 128
    float* sS   = mS + 128;                        // 128
    __shared__ __align__(8) unsigned long long mbar[2];

    const int tid = threadIdx.x, wid = tid >> 5, lane = tid & 31;
    const bool isL1 = blockIdx.x >= 32;
    const int c = isL1 ? (int)blockIdx.x - 32 : (int)blockIdx.x;
    const uint32_t mb0 = smem_u32(&mbar[0]), mb1 = smem_u32(&mbar[1]);

    if (tid == 0) { MBAR_INIT(mb0, 1); MBAR_INIT(mb1, 1); }
    __syncthreads();
    int ph0 = 0, ph1 = 0;

    float creg[4] = {0.f, 0.f, 0.f, 0.f};

    for (int t = 0; t <= Tn; t++) {
        if (!isL1 && t < Tn) {
            const int u = t;
            const unsigned char* Ah = g_W0f + (size_t)c * 262144;
            const unsigned char* Bg = g_h0B[u & 1];
            const int mt = wid & 7, nh = wid >> 3;
            if (tid == 0) {
                MBAR_EXPECT(mb0, 65536);
                bulk_g2s(smem_u32(sm), Bg, 65536, mb0);
                MBAR_EXPECT(mb1, 65536);
                bulk_g2s(smem_u32(sm + 65536), Bg + 65536, 65536, mb1);
            }
            // A prefetch depth 2 (before B wait)
            uint4 areg0 = *(const uint4*)(Ah + ((size_t)mt << 9) + lane * 16);
            uint4 areg1 = *(const uint4*)(Ah + ((size_t)(8 + mt) << 9) + lane * 16);
            MBAR_WAIT(mb0, (uint32_t)(ph0 & 1)); ph0++;
            uint2 breg[4];
            {
                const unsigned char* bb = sm + (nh << 10);
#pragma unroll
                for (int j = 0; j < 4; j++)
                    breg[j] = *(const uint2*)(bb + (j << 8) + lane * 8);
            }
            float acc[4][4] = {};
            for (int kt = 0; kt < 64; kt++) {
                uint4 an;
                if (kt < 62)
                    an = *(const uint4*)(Ah + ((size_t)((kt + 2) * 8 + mt) << 9) + lane * 16);
                uint2 bn[4];
                if (kt < 63) {
                    if (kt == 31) { MBAR_WAIT(mb1, (uint32_t)(ph1 & 1)); ph1++; }
                    const unsigned char* bb = sm + ((kt + 1) << 11) + (nh << 10);
#pragma unroll
                    for (int j = 0; j < 4; j++)
                        bn[j] = *(const uint2*)(bb + (j << 8) + lane * 8);
                }
                uint4 ac = (kt & 1) ? areg1 : areg0;
#pragma unroll
                for (int j = 0; j < 4; j++) MMAH(acc[j], ac, breg[j]);
                if (kt < 62) { if (kt & 1) areg1 = an; else areg0 = an; }
                if (kt < 63) {
#pragma unroll
                    for (int j = 0; j < 4; j++) breg[j] = bn[j];
                }
            }
            __syncthreads();
            // ---------------- epilogue L0 ----------------
            float s0 = 0.f, q0 = 0.f, s1 = 0.f, q1 = 0.f;
            int r0 = mt * 16 + (lane >> 2);
#pragma unroll
            for (int j = 0; j < 4; j++) {
                int cl = (nh * 4 + j) * 8 + (lane & 3) * 2;
                Cs[r0][cl] = acc[j][0]; Cs[r0][cl + 1] = acc[j][1];
                Cs[r0 + 8][cl] = acc[j][2]; Cs[r0 + 8][cl + 1] = acc[j][3];
                s0 += acc[j][0] + acc[j][1];
                q0 += acc[j][0] * acc[j][0] + acc[j][1] * acc[j][1];
                s1 += acc[j][2] + acc[j][3];
                q1 += acc[j][2] * acc[j][2] + acc[j][3] * acc[j][3];
            }
            s0 += __shfl_xor_sync(0xffffffffu, s0, 1); s0 += __shfl_xor_sync(0xffffffffu, s0, 2);
            q0 += __shfl_xor_sync(0xffffffffu, q0, 1); q0 += __shfl_xor_sync(0xffffffffu, q0, 2);
            s1 += __shfl_xor_sync(0xffffffffu, s1, 1); s1 += __shfl_xor_sync(0xffffffffu, s1, 2);
            q1 += __shfl_xor_sync(0xffffffffu, q1, 1); q1 += __shfl_xor_sync(0xffffffffu, q1, 2);
            if ((lane & 3) == 0) {
                prS[r0 * 2 + nh] = s0; pqS[r0 * 2 + nh] = q0;
                prS[(r0 + 8) * 2 + nh] = s1; pqS[(r0 + 8) * 2 + nh] = q1;
            }
            __syncthreads();
            if (tid < 128) {
                float s = prS[tid * 2] + prS[tid * 2 + 1];
                float q = pqS[tid * 2] + pqS[tid * 2 + 1];
                float m = s * (1.f / 64.f);
                float var = fmaxf(q * (1.f / 64.f) - m * m, 0.f);
                float gam = gh0[(tid >> 5) * Hn + c * 32 + (tid & 31)];
                mS[tid] = m; sS[tid] = gam * rsqrtf(var + 1e-5f);
            }
            __syncthreads();
            int hcl = tid & 31, bg = tid >> 5;
            int hc = c * 32 + hcl;
            float m0 = mS[hcl], c0s = sS[hcl];
            float m1 = mS[32 + hcl], c1s = sS[32 + hcl];
            float m2 = mS[64 + hcl], c2s = sS[64 + hcl];
            float m3 = mS[96 + hcl], c3s = sS[96 + hcl];
            float ov[4], ps = 0.f, p2 = 0.f;
            float bI = b0[hc], bJ = b0[Hn + hc], bF = b0[2 * Hn + hc], bO = b0[3 * Hn + hc];
#pragma unroll
            for (int i = 0; i < 4; i++) {
                int b_ = bg * 4 + i;
                const float* gx = g_GX0 + (size_t)(u * 64 + b_) * FH;
                float preI = (Cs[hcl][b_] - m0) * c0s       + gx[hc]          + bI;
                float preJ = (Cs[32 + hcl][b_] - m1) * c1s  + gx[Hn + hc]     + bJ;
                float preF = (Cs[64 + hcl][b_] - m2) * c2s  + gx[2 * Hn + hc] + bF;
                float preO = (Cs[96 + hcl][b_] - m3) * c3s  + gx[3 * Hn + hc] + bO;
                float cn = sigm(preF + 1.f) * creg[i] + sigm(preI) * tanhf(preJ);
                creg[i] = cn; ov[i] = preO; ps += cn; p2 += cn * cn;
            }
            psA[bg * 32 + hcl] = ps; ps2A[bg * 32 + hcl] = p2;
            __syncthreads();
            if (tid < 32) {
                float s = 0.f, s2 = 0.f;
#pragma unroll
                for (int g = 0; g < 16; g++) { s += psA[g * 32 + tid]; s2 += ps2A[g * 32 + tid]; }
                float m = s * (1.f / 64.f);
                float var = fmaxf(s2 * (1.f / 64.f) - m * m, 0.f);
                mcA[tid] = m; rsA[tid] = rsqrtf(var + 1e-5f);
            }
            __syncthreads();
            float gcv = gc0[hc], bcv = bc0[hc], mm = mcA[hcl], rr = rsA[hcl];
            unsigned char* hb = g_h0B[(u + 1) & 1];
#pragma unroll
            for (int i = 0; i < 4; i++) {
                float cn = gcv * (creg[i] - mm) * rr + bcv;
                float h = sigm(ov[i]) * tanhf(cn);
                write_hfrag(hb, bg * 4 + i, hc, h);
            }
        } else if (isL1 && t >= 1) {
            const int u = t - 1;
            const int g = wid >> 3, mt = (wid >> 1) & 3, nh = wid & 1;
            const unsigned char* Ag = (g == 0 ? g_W1xf : g_W1hf) + (size_t)c * 131072;
            const unsigned char* Bi0 = g_h0B[(u + 1) & 1];
            const unsigned char* Bi1 = g_h1B[u & 1];
            const int gsel = g * 32768;
            if (tid == 0) {
#pragma unroll
                for (int k0 = 0; k0 < 2; k0++) {
                    uint32_t mbk = k0 ? mb1 : mb0;
                    uint32_t slot = smem_u32(sm + k0 * 65536);
                    MBAR_EXPECT(mbk, 65536);
                    bulk_g2s(slot, Bi0 + k0 * 32768, 32768, mbk);
                    bulk_g2s(slot + 32768, Bi1 + k0 * 32768, 32768, mbk);
                }
            }
            uint4 areg0 = *(const uint4*)(Ag + ((size_t)mt << 9) + lane * 16);
            uint4 areg1 = *(const uint4*)(Ag + ((size_t)(4 + mt) << 9) + lane * 16);
            MBAR_WAIT(mb0, (uint32_t)(ph0 & 1)); ph0++;
            uint2 breg[4];
            {
                const unsigned char* bb = sm + gsel + (nh << 10);
#pragma unroll
                for (int j = 0; j < 4; j++)
                    breg[j] = *(const uint2*)(bb + (j << 8) + lane * 8);
            }
            float acc[4][4] = {};
            for (int kt = 0; kt < 64; kt++) {
                int kc = kt >> 4;
                uint4 an;
                if (kt < 62)
                    an = *(const uint4*)(Ag + ((size_t)((kt + 2) * 4 + mt) << 9) + lane * 16);
                uint2 bn[4];
                if (kt < 63) {
                    int kn = kt + 1;
                    if ((kn & 15) == 0) {
                        if ((kn >> 4) & 1) { MBAR_WAIT(mb1, (uint32_t)(ph1 & 1)); ph1++; }
                        else               { MBAR_WAIT(mb0, (uint32_t)(ph0 & 1)); ph0++; }
                    }
                    const unsigned char* bb = sm + (((kn >> 4) & 1) * 65536) + gsel
                                            + ((kn & 15) << 11) + (nh << 10);
#pragma unroll
                    for (int j = 0; j < 4; j++)
                        bn[j] = *(const uint2*)(bb + (j << 8) + lane * 8);
                }
                uint4 ac = (kt & 1) ? areg1 : areg0;
#pragma unroll
                for (int j = 0; j < 4; j++) MMAH(acc[j], ac, breg[j]);
                if (kt < 62) { if (kt & 1) areg1 = an; else areg0 = an; }
                if (kt < 63) {
#pragma unroll
                    for (int j = 0; j < 4; j++) breg[j] = bn[j];
                }
                if ((kt & 15) == 15 && kc < 2) {
                    __syncthreads();
                    if (tid == 0) {
                        uint32_t mbk = (kc & 1) ? mb1 : mb0;
                        uint32_t slot = smem_u32(sm + (kc & 1) * 65536);
                        MBAR_EXPECT(mbk, 65536);
                        bulk_g2s(slot, Bi0 + (kc + 2) * 32768, 32768, mbk);
                        bulk_g2s(slot + 32768, Bi1 + (kc + 2) * 32768, 32768, mbk);
                    }
                }
            }
            __syncthreads();
            // ---------------- epilogue L1 ----------------
            float s0 = 0.f, q0 = 0.f, s1 = 0.f, q1 = 0.f;
            int r0 = g * 64 + mt * 16 + (lane >> 2);
#pragma unroll
            for (int j = 0; j < 4; j++) {
                int cl = (nh * 4 + j) * 8 + (lane & 3) * 2;
                Cs[r0][cl] = acc[j][0]; Cs[r0][cl + 1] = acc[j][1];
                Cs[r0 + 8][cl] = acc[j][2]; Cs[r0 + 8][cl + 1] = acc[j][3];
                s0 += acc[j][0] + acc[j][1];
                q0 += acc[j][0] * acc[j][0] + acc[j][1] * acc[j][1];
                s1 += acc[j][2] + acc[j][3];
                q1 += acc[j][2] * acc[j][2] + acc[j][3] * acc[j][3];
            }
            s0 += __shfl_xor_sync(0xffffffffu, s0, 1); s0 += __shfl_xor_sync(0xffffffffu, s0, 2);
            q0 += __shfl_xor_sync(0xffffffffu, q0, 1); q0 += __shfl_xor_sync(0xffffffffu, q0, 2);
            s1 += __shfl_xor_sync(0xffffffffu, s1, 1); s1 += __shfl_xor_sync(0xffffffffu, s1, 2);
            q1 += __shfl_xor_sync(0xffffffffu, q1, 1); q1 += __shfl_xor_sync(0xffffffffu, q1, 2);
            if ((lane & 3) == 0) {
                prS[r0 * 2 + nh] = s0; pqS[r0 * 2 + nh] = q0;
                prS[(r0 + 8) * 2 + nh] = s1; pqS[(r0 + 8) * 2 + nh] = q1;
            }
            __syncthreads();
            if (tid < 128) {
                float s = prS[tid * 2] + prS[tid * 2 + 1];
                float q = pqS[tid * 2] + pqS[tid * 2 + 1];
                float m = s * (1.f / 64.f);
                float var = fmaxf(q * (1.f / 64.f) - m * m, 0.f);
                int rr_ = tid & 63;
                int gi = (rr_ >> 4) * Hn + c * 16 + (rr_ & 15);
                float gam = (tid < 64) ? gx1[gi] : gh1[gi];
                mS[tid] = m; sS[tid] = gam * rsqrtf(var + 1e-5f);
            }
            __syncthreads();
            int hcl = tid & 15, bg = tid >> 4;
            int hc = c * 16 + hcl;
            float ov[2], ps = 0.f, p2 = 0.f;
            float bI = b1[hc], bJ = b1[Hn + hc], bF = b1[2 * Hn + hc], bO = b1[3 * Hn + hc];
#pragma unroll
            for (int i = 0; i < 2; i++) {
                int b_ = bg * 2 + i;
                float preI = (Cs[hcl][b_] - mS[hcl]) * sS[hcl]
                           + (Cs[64 + hcl][b_] - mS[64 + hcl]) * sS[64 + hcl] + bI;
                float preJ = (Cs[16 + hcl][b_] - mS[16 + hcl]) * sS[16 + hcl]
                           + (Cs[80 + hcl][b_] - mS[80 + hcl]) * sS[80 + hcl] + bJ;
                float preF = (Cs[32 + hcl][b_] - mS[32 + hcl]) * sS[32 + hcl]
                           + (Cs[96 + hcl][b_] - mS[96 + hcl]) * sS[96 + hcl] + bF;
                float preO = (Cs[48 + hcl][b_] - mS[48 + hcl]) * sS[48 + hcl]
                           + (Cs[112 + hcl][b_] - mS[112 + hcl]) * sS[112 + hcl] + bO;
                float cn = sigm(preF + 1.f) * creg[i] + sigm(preI) * tanhf(preJ);
                creg[i] = cn; ov[i] = preO; ps += cn; p2 += cn * cn;
            }
            psA[bg * 16 + hcl] = ps; ps2A[bg * 16 + hcl] = p2;
            __syncthreads();
            if (tid < 16) {
                float s = 0.f, s2 = 0.f;
#pragma unroll
                for (int gg = 0; gg < 32; gg++) { s += psA[gg * 16 + tid]; s2 += ps2A[gg * 16 + tid]; }
                float m = s * (1.f / 64.f);
                float var = fmaxf(s2 * (1.f / 64.f) - m * m, 0.f);
                mcA[tid] = m; rsA[tid] = rsqrtf(var + 1e-5f);
            }
            __syncthreads();
            float gcv = gc1[hc], bcv = bc1[hc], mm = mcA[hcl], rr = rsA[hcl];
            unsigned char* hb = g_h1B[(u + 1) & 1];
#pragma unroll
            for (int i = 0; i < 2; i++) {
                int b_ = bg * 2 + i;
                float cn = gcv * (creg[i] - mm) * rr + bcv;
                float h = sigm(ov[i]) * tanhf(cn);
                write_hfrag(hb, b_, hc, h);
                __nv_bfloat16 hhi = __float2bfloat16(h);
                __nv_bfloat16 hlo = __float2bfloat16(h - __bfloat162float(hhi));
                size_t off = afrag_off1k(b_ * Tn + u, hc);
                *(__nv_bfloat16*)(g_Hf + off) = hhi;
                *(__nv_bfloat16*)(g_Hf + HPLANE + off) = hlo;
            }
        }
        grid_bar();
    }
}

// ------------------------------ launch ------------------------------------
extern "C" void kernel_launch(void* const* d_in, const int* in_sizes, int n_in,
                              void* d_out, int out_size) {
    const int*   inp = (const int*)  d_in[0];
    const float* emb = (const float*)d_in[1];
    const float* Wx0 = (const float*)d_in[2];
    const float* Wh0 = (const float*)d_in[3];
    const float* b0  = (const float*)d_in[4];
    const float* gx0 = (const float*)d_in[5];
    const float* gh0 = (const float*)d_in[6];
    const float* gc0 = (const float*)d_in[7];
    const float* bc0 = (const float*)d_in[8];
    const float* Wx1 = (const float*)d_in[9];
    const float* Wh1 = (const float*)d_in[10];
    const float* b1  = (const float*)d_in[11];
    const float* gx1 = (const float*)d_in[12];
    const float* gh1 = (const float*)d_in[13];
    const float* gc1 = (const float*)d_in[14];
    const float* bc1 = (const float*)d_in[15];
    const float* Wp  = (const float*)d_in[16];
    const float* bp  = (const float*)d_in[17];
    const float* sw  = (const float*)d_in[18];
    const float* sb  = (const float*)d_in[19];
    float* out = (float*)d_out;

    unsigned char *pXf, *pYf, *pWx0B, *pswB;
    cudaGetSymbolAddress((void**)&pXf,  g_Xf);
    cudaGetSymbolAddress((void**)&pYf,  g_Yf);
    cudaGetSymbolAddress((void**)&pWx0B, g_Wx0B);
    cudaGetSymbolAddress((void**)&pswB,  g_swB);

    cudaFuncSetAttribute(k_scan, cudaFuncAttributeMaxDynamicSharedMemorySize, 138496);
    cudaFuncSetAttribute(k_gemm_mma, cudaFuncAttributeMaxDynamicSharedMemorySize, 65536);
    cudaFuncSetAttribute(k_gemm_gx0, cudaFuncAttributeMaxDynamicSharedMemorySize, 65536);
    cudaFuncSetAttribute(k_gemm_wp, cudaFuncAttributeMaxDynamicSharedMemorySize, 131072);

    k_embed<<<Tn * Bn, 256>>>(inp, emb);
    k_prepw<<<dim3(16384, 3), 256>>>(Wh0, Wx1, Wh1);
    k_prepB<<<(NUn * (FH + Vn)) / 256, 256>>>(Wx0, sw);
    k_prepWp<<<(Hn * NUn) / 256, 256>>>(Wp);
    k_gemm_gx0<<<dim3(FH / 64, 64), 256, 65536>>>(pXf, pWx0B, gx0);
    k_scan<<<NBLK, 512, 138496>>>(b0, gh0, gc0, bc0, b1, gx1, gh1, gc1, bc1);
    k_gemm_wp<<<dim3(NUn / 64, 64), 256, 131072>>>(bp);
    k_gemm_mma<<<dim3(Vn / 64, 64), 256, 65536>>>(pYf, pswB, sb, out, Vn);
}

// round 15
// speedup vs baseline: 1.3263x; 1.3263x over previous
#include <cuda_runtime.h>
#include <cuda_bf16.h>
#include <cuda_fp16.h>
#include <cstdint>
#include <math.h>

#define Tn   128
#define Bn   64
#define Hn   1024
#define NUn  256
#define Vn   8000
#define FH   4096
#define NBLK 96
#define APLANE 4194304    // 8192*512: one plane of a K=256 A-frag image
#define HPLANE 16777216   // 8192*2048: one plane of the K=1024 H1 A-frag image

// ------------------------------ device scratch ----------------------------
__device__ float g_GX0[Tn * Bn * FH];     // BN(x@Wx0) with gx0 folded

// scan weights: A-fragment images, SINGLE fp16 plane per CTA slice
__device__ __align__(16) unsigned char g_W0f [32 * 262144];
__device__ __align__(16) unsigned char g_W1xf[64 * 131072];
__device__ __align__(16) unsigned char g_W1hf[64 * 131072];
// h states as B-fragment images, single fp16 plane: [parity][128KB]
__device__ __align__(16) unsigned char g_h0B[2][131072];
__device__ __align__(16) unsigned char g_h1B[2][131072];
// A-frag images
__device__ __align__(16) unsigned char g_Xf[2 * APLANE];   // X, K=256, bf16 hi|lo
__device__ __align__(16) unsigned char g_Yh[APLANE];       // Y, K=256, fp16 single
__device__ __align__(16) unsigned char g_Hf[2 * HPLANE];   // H1, K=1024, bf16 hi|lo
// B-frag images
__device__ __align__(16) unsigned char g_Wx0B[2 * 4096 * 512];  // bf16 hi|lo
__device__ __align__(16) unsigned char g_swH [8000 * 512];      // fp16 single
__device__ __align__(16) unsigned char g_WpB [2 * 4 * 131072];  // bf16 hi|lo

__device__ unsigned g_barCnt;
__device__ volatile unsigned g_barGen;

__device__ __forceinline__ float sigm(float x) { return __fdividef(1.f, 1.f + __expf(-x)); }

#define MMAB(c, a, b) \
    asm volatile("mma.sync.aligned.m16n8k16.row.col.f32.bf16.bf16.f32 " \
        "{%0,%1,%2,%3},{%4,%5,%6,%7},{%8,%9},{%0,%1,%2,%3};" \
        : "+f"((c)[0]), "+f"((c)[1]), "+f"((c)[2]), "+f"((c)[3]) \
        : "r"((a).x), "r"((a).y), "r"((a).z), "r"((a).w), "r"((b).x), "r"((b).y))
#define MMAH(c, a, b) \
    asm volatile("mma.sync.aligned.m16n8k16.row.col.f32.f16.f16.f32 " \
        "{%0,%1,%2,%3},{%4,%5,%6,%7},{%8,%9},{%0,%1,%2,%3};" \
        : "+f"((c)[0]), "+f"((c)[1]), "+f"((c)[2]), "+f"((c)[3]) \
        : "r"((a).x), "r"((a).y), "r"((a).z), "r"((a).w), "r"((b).x), "r"((b).y))

__device__ __forceinline__ uint32_t smem_u32(const void* p) {
    uint32_t a;
    asm("{ .reg .u64 t; cvta.to.shared.u64 t, %1; cvt.u32.u64 %0, t; }" : "=r"(a) : "l"(p));
    return a;
}
__device__ __forceinline__ void cpa16(uint32_t dst, const void* src) {
    asm volatile("cp.async.cg.shared.global [%0], [%1], 16;" :: "r"(dst), "l"(src) : "memory");
}
#define CP_COMMIT() asm volatile("cp.async.commit_group;" ::: "memory")
#define CP_WAIT(n)  asm volatile("cp.async.wait_group %0;" :: "n"(n) : "memory")

__device__ __forceinline__ void bulk_g2s(uint32_t dst, const void* src, uint32_t bytes, uint32_t mbar) {
    asm volatile(
        "cp.async.bulk.shared::cluster.global.mbarrier::complete_tx::bytes [%0], [%1], %2, [%3];"
        :: "r"(dst), "l"(src), "r"(bytes), "r"(mbar) : "memory");
}
#define MBAR_INIT(a, n) \
    asm volatile("mbarrier.init.shared.b64 [%0], %1;" :: "r"(a), "r"((uint32_t)(n)) : "memory")
#define MBAR_EXPECT(a, n) \
    asm volatile("mbarrier.arrive.expect_tx.shared.b64 _, [%0], %1;" :: "r"(a), "r"((uint32_t)(n)) : "memory")
#define MBAR_WAIT(a, ph) do {                                                  \
    uint32_t _m = (a), _p = (ph), _d;                                          \
    asm volatile("{\n\t.reg .pred p;\n\t"                                      \
        "mbarrier.try_wait.parity.acquire.cta.shared::cta.b64 p, [%1], %2;\n\t"\
        "selp.b32 %0, 1, 0, p;\n\t}"                                           \
        : "=r"(_d) : "r"(_m), "r"(_p) : "memory");                             \
    if (!_d) {                                                                 \
        asm volatile("{\n\t.reg .pred P1;\n\t"                                 \
            "W_%=:\n\t"                                                        \
            "mbarrier.try_wait.parity.acquire.cta.shared::cta.b64 P1, [%0], %1, 0x989680;\n\t" \
            "@P1 bra.uni D_%=;\n\tbra.uni W_%=;\n\tD_%=:\n\t}"                 \
            :: "r"(_m), "r"(_p) : "memory");                                   \
    }                                                                          \
} while (0)

__device__ __forceinline__ void grid_bar() {
    __syncthreads();
    if (threadIdx.x == 0) {
        unsigned gen = g_barGen;
        __threadfence();
        if (atomicAdd(&g_barCnt, 1u) == NBLK - 1) {
            g_barCnt = 0;
            __threadfence();
            g_barGen = gen + 1;
        } else {
            while (g_barGen == gen) { __nanosleep(64); }
        }
        __threadfence();
    }
    __syncthreads();
}

// A-fragment offset, K=256 image
__device__ __forceinline__ size_t afrag_off(int m, int k) {
    int mt = m >> 4, mi = m & 15, kt = k >> 4, ki = k & 15;
    int lane = (mi & 7) * 4 + ((ki & 7) >> 1);
    int reg  = (mi >> 3) + ((ki >> 3) << 1);
    return ((size_t)(mt * 16 + kt) << 9) + lane * 16 + (reg << 2) + ((ki & 1) << 1);
}
// A-fragment offset, K=1024 image
__device__ __forceinline__ size_t afrag_off1k(int m, int k) {
    int mt = m >> 4, mi = m & 15, kt = k >> 4, ki = k & 15;
    int lane = (mi & 7) * 4 + ((ki & 7) >> 1);
    int reg  = (mi >> 3) + ((ki >> 3) << 1);
    return ((size_t)(mt * 64 + kt) << 9) + lane * 16 + (reg << 2) + ((ki & 1) << 1);
}
// B-fragment offset, K=256 image (ntile-major)
__device__ __forceinline__ size_t bfrag_off(int k, int n) {
    int nt = n >> 3, ni = n & 7, kt = k >> 4, ki = k & 15;
    int ln = ni * 4 + ((ki & 7) >> 1);
    return ((size_t)(nt * 16 + kt) << 8) + ln * 8 + ((ki >> 3) << 2) + ((ki & 1) << 1);
}

// write one h value into the scan B-frag plane (kt-major tiles, K=1024), fp16
__device__ __forceinline__ void write_hfrag(unsigned char* hb, int b, int hc, float h) {
    int kt = hc >> 4, nt = b >> 3, ki = hc & 15, ni = b & 7;
    int ln = ni * 4 + ((ki & 7) >> 1);
    int off = ((kt * 8 + nt) << 8) + ln * 8 + ((ki >> 3) << 2) + ((ki & 1) << 1);
    *(__half*)(hb + off) = __float2half(h);
}

// ------------------------------ embedding + state init --------------------
__global__ void k_embed(const int* __restrict__ inp, const float* __restrict__ emb) {
    int row = blockIdx.x;                 // t*64 + b
    int u = threadIdx.x;
    int i = blockIdx.x * 256 + threadIdx.x;
    if (i < 65536) ((uint32_t*)g_h0B)[i] = 0u;
    else if (i < 131072) ((uint32_t*)g_h1B)[i - 65536] = 0u;
    int t = row >> 6, b = row & 63;
    float v = emb[(size_t)inp[b * Tn + t] * NUn + u];
    __nv_bfloat16 hi = __float2bfloat16(v);
    __nv_bfloat16 lo = __float2bfloat16(v - __bfloat162float(hi));
    size_t off = afrag_off(row, u);
    *(__nv_bfloat16*)(g_Xf + off) = hi;
    *(__nv_bfloat16*)(g_Xf + APLANE + off) = lo;
}

// ------------------------------ weights -> B-frags ------------------------
// Wx0: bf16 hi|lo.  softmax_w: fp16 single plane.
__global__ void k_prepB(const float* __restrict__ Wx0, const float* __restrict__ sw) {
    int idx = blockIdx.x * 256 + threadIdx.x;
    if (idx < NUn * FH) {
        int k = idx / FH, n = idx - k * FH;
        float v = Wx0[idx];
        __nv_bfloat16 hi = __float2bfloat16(v);
        __nv_bfloat16 lo = __float2bfloat16(v - __bfloat162float(hi));
        size_t off = bfrag_off(k, n);
        *(__nv_bfloat16*)(g_Wx0B + off) = hi;
        *(__nv_bfloat16*)(g_Wx0B + (size_t)FH * 512 + off) = lo;
    } else {
        int local = idx - NUn * FH;
        int k = local / Vn, n = local - k * Vn;
        *(__half*)(g_swH + bfrag_off(k, n)) = __float2half(sw[local]);
    }
}

// ------------------------------ Wp -> B-frags (K=1024, chunk-contiguous) --
__global__ void k_prepWp(const float* __restrict__ Wp) {
    int idx = blockIdx.x * 256 + threadIdx.x;   // k*256 + n
    int k = idx >> 8, n = idx & 255;
    float v = Wp[idx];
    __nv_bfloat16 hi = __float2bfloat16(v);
    __nv_bfloat16 lo = __float2bfloat16(v - __bfloat162float(hi));
    int nb = n >> 6, ntl = (n >> 3) & 7, ni = n & 7;
    int kt = k >> 4, ki = k & 15;
    int ln = ni * 4 + ((ki & 7) >> 1);
    size_t off = (size_t)nb * 131072 + ((size_t)(kt * 8 + ntl) << 8)
               + ln * 8 + ((ki >> 3) << 2) + ((ki & 1) << 1);
    *(__nv_bfloat16*)(g_WpB + off) = hi;
    *(__nv_bfloat16*)(g_WpB + 524288 + off) = lo;
}

// ------------------------------ scan weight prep (single fp16) ------------
__global__ void k_prepw(const float* __restrict__ Wh0, const float* __restrict__ Wx1,
                        const float* __restrict__ Wh1) {
    int which = blockIdx.y;
    const float* W = which == 0 ? Wh0 : (which == 1 ? Wx1 : Wh1);
    int idx = blockIdx.x * 256 + threadIdx.x;   // k*4096 + gcol
    int k = idx >> 12, gcol = idx & 4095;
    __half hv = __float2half(W[idx]);
    int g = gcol >> 10, hc = gcol & 1023;
    unsigned char* base;
    int MT, m;
    if (which == 0) {
        int c = hc >> 5; m = g * 32 + (hc & 31); MT = 8;
        base = g_W0f + (size_t)c * 262144;
    } else {
        int c = hc >> 4; m = g * 16 + (hc & 15); MT = 4;
        base = (which == 1 ? g_W1xf : g_W1hf) + (size_t)c * 131072;
    }
    int kt = k >> 4, ki = k & 15, mt = m >> 4, mi = m & 15;
    int lane = (mi & 7) * 4 + ((ki & 7) >> 1);
    int reg  = (mi >> 3) + ((ki >> 3) << 1);
    int off  = ((kt * MT + mt) << 9) + lane * 16 + (reg << 2) + ((ki & 1) << 1);
    *(__half*)(base + off) = hv;
}

// ------------------------------ GX0 MMA with fused per-timestep BN --------
__global__ void __launch_bounds__(256) k_gemm_gx0(
        const unsigned char* __restrict__ Af, const unsigned char* __restrict__ Bf,
        const float* __restrict__ gx0) {
    extern __shared__ unsigned char sb[];
    const int tid = threadIdx.x, w = tid >> 5, lane = tid & 31;
    const int nb = blockIdx.x, mb = blockIdx.y;
    {
        int p = tid >> 7, o = (tid & 127) * 16;
        const unsigned char* src = Bf + (size_t)p * ((size_t)FH * 512) + (size_t)nb * 32768 + o;
        uint32_t dst = smem_u32(sb + p * 32768 + o);
#pragma unroll
        for (int i = 0; i < 16; i++) cpa16(dst + i * 2048, src + i * 2048);
        CP_COMMIT(); CP_WAIT(0);
    }
    __syncthreads();
    const size_t abase = ((size_t)(mb * 8 + w) << 13) + lane * 16;
    uint4 ahc = *(const uint4*)(Af + abase);
    uint4 alc = *(const uint4*)(Af + APLANE + abase);
    float acc[8][4] = {};
#pragma unroll
    for (int kt = 0; kt < 16; kt++) {
        uint4 ahn, aln;
        if (kt < 15) {
            ahn = *(const uint4*)(Af + abase + (kt + 1) * 512);
            aln = *(const uint4*)(Af + APLANE + abase + (kt + 1) * 512);
        }
        uint2 bh[8], bl[8];
#pragma unroll
        for (int j = 0; j < 8; j++) {
            bh[j] = *(const uint2*)(sb + (j * 16 + kt) * 256 + lane * 8);
            bl[j] = *(const uint2*)(sb + 32768 + (j * 16 + kt) * 256 + lane * 8);
        }
#pragma unroll
        for (int j = 0; j < 8; j++) MMAB(acc[j], ahc, bh[j]);
#pragma unroll
        for (int j = 0; j < 8; j++) MMAB(acc[j], alc, bh[j]);
#pragma unroll
        for (int j = 0; j < 8; j++) MMAB(acc[j], ahc, bl[j]);
        ahc = ahn; alc = aln;
    }
    __syncthreads();
    float (*Cs)[65] = (float(*)[65])sb;
    float* mS = (float*)(sb + 33280);
    float* sS = (float*)(sb + 33792);
    int r0 = w * 16 + (lane >> 2);
#pragma unroll
    for (int j = 0; j < 8; j++) {
        int cl = j * 8 + (lane & 3) * 2;
        Cs[r0][cl] = acc[j][0]; Cs[r0][cl + 1] = acc[j][1];
        Cs[r0 + 8][cl] = acc[j][2]; Cs[r0 + 8][cl + 1] = acc[j][3];
    }
    __syncthreads();
    if (tid < 128) {
        int half = tid >> 6, col = tid & 63;
        float s = 0.f, s2 = 0.f;
#pragma unroll
        for (int b = 0; b < 64; b++) {
            float v = Cs[half * 64 + b][col];
            s += v; s2 += v * v;
        }
        float m = s * (1.f / 64.f);
        float var = fmaxf(s2 * (1.f / 64.f) - m * m, 0.f);
        mS[tid] = m;
        sS[tid] = gx0[nb * 64 + col] * rsqrtf(var + 1e-5f);
    }
    __syncthreads();
    {
        int col = tid & 63, seg = tid >> 6;
#pragma unroll
        for (int i = 0; i < 32; i++) {
            int rr = seg * 32 + i;
            int sidx = (rr >> 6) * 64 + col;
            g_GX0[(size_t)(mb * 128 + rr) * FH + nb * 64 + col] =
                sS[sidx] * (Cs[rr][col] - mS[sidx]);
        }
    }
}

// ------------------------------ logits MMA GEMM, K=256 (fp16, 1-product) --
__global__ void __launch_bounds__(256) k_gemm_logits(
        const float* __restrict__ bias, float* __restrict__ C) {
    extern __shared__ unsigned char sb[];
    const int tid = threadIdx.x, w = tid >> 5, lane = tid & 31;
    const int nb = blockIdx.x, mb = blockIdx.y;
    {
        int o = tid * 16;
        const unsigned char* src = g_swH + (size_t)nb * 32768 + o;
        uint32_t dst = smem_u32(sb + o);
#pragma unroll
        for (int i = 0; i < 8; i++) cpa16(dst + i * 4096, src + i * 4096);
        CP_COMMIT(); CP_WAIT(0);
    }
    __syncthreads();
    const size_t abase = ((size_t)(mb * 8 + w) << 13) + lane * 16;
    uint4 ac = *(const uint4*)(g_Yh + abase);
    float acc[8][4] = {};
#pragma unroll
    for (int kt = 0; kt < 16; kt++) {
        uint4 an;
        if (kt < 15) an = *(const uint4*)(g_Yh + abase + (kt + 1) * 512);
        uint2 bh[8];
#pragma unroll
        for (int j = 0; j < 8; j++)
            bh[j] = *(const uint2*)(sb + (j * 16 + kt) * 256 + lane * 8);
#pragma unroll
        for (int j = 0; j < 8; j++) MMAH(acc[j], ac, bh[j]);
        ac = an;
    }
    int r0 = mb * 128 + w * 16 + (lane >> 2);
#pragma unroll
    for (int j = 0; j < 8; j++) {
        int col = nb * 64 + j * 8 + (lane & 3) * 2;
        float b0v = bias[col], b1v = bias[col + 1];
        *(float2*)(C + (size_t)r0 * Vn + col) = make_float2(acc[j][0] + b0v, acc[j][1] + b1v);
        *(float2*)(C + (size_t)(r0 + 8) * Vn + col) = make_float2(acc[j][2] + b0v, acc[j][3] + b1v);
    }
}

// ------------------------------ Wp MMA GEMM, K=1024 -----------------------
// Y = Hf @ WpB + bp, written directly as fp16 A-frags (g_Yh).
__global__ void __launch_bounds__(256) k_gemm_wp(const float* __restrict__ bp) {
    extern __shared__ unsigned char sb[];
    __shared__ __align__(8) unsigned long long mbar[2];
    const int tid = threadIdx.x, w = tid >> 5, lane = tid & 31;
    const int nb = blockIdx.x, mb = blockIdx.y;
    const uint32_t mb0 = smem_u32(&mbar[0]), mb1 = smem_u32(&mbar[1]);
    if (tid == 0) { MBAR_INIT(mb0, 1); MBAR_INIT(mb1, 1); }
    __syncthreads();
    const unsigned char* Bbase = g_WpB + (size_t)nb * 131072;
    if (tid == 0) {
#pragma unroll
        for (int k0 = 0; k0 < 2; k0++) {
            uint32_t mbk = k0 ? mb1 : mb0;
            uint32_t slot = smem_u32(sb + k0 * 65536);
            MBAR_EXPECT(mbk, 65536);
            bulk_g2s(slot, Bbase + k0 * 32768, 32768, mbk);
            bulk_g2s(slot + 32768, Bbase + 524288 + k0 * 32768, 32768, mbk);
        }
    }
    const size_t abase = ((size_t)(mb * 8 + w) << 15) + lane * 16;
    int ph0 = 0, ph1 = 0;
    uint4 ahc = *(const uint4*)(g_Hf + abase);
    uint4 alc = *(const uint4*)(g_Hf + HPLANE + abase);
    float acc[8][4] = {};
    for (int kt = 0; kt < 64; kt++) {
        int kc = kt >> 4;
        if ((kt & 15) == 0) {
            if (kc & 1) { MBAR_WAIT(mb1, (uint32_t)(ph1 & 1)); ph1++; }
            else        { MBAR_WAIT(mb0, (uint32_t)(ph0 & 1)); ph0++; }
        }
        uint4 ahn, aln;
        if (kt < 63) {
            ahn = *(const uint4*)(g_Hf + abase + ((size_t)(kt + 1) << 9));
            aln = *(const uint4*)(g_Hf + HPLANE + abase + ((size_t)(kt + 1) << 9));
        }
        const unsigned char* bb = sb + (kc & 1) * 65536 + ((kt & 15) << 11);
        uint2 bh[8], bl[8];
#pragma unroll
        for (int j = 0; j < 8; j++) {
            bh[j] = *(const uint2*)(bb + (j << 8) + lane * 8);
            bl[j] = *(const uint2*)(bb + 32768 + (j << 8) + lane * 8);
        }
#pragma unroll
        for (int j = 0; j < 8; j++) MMAB(acc[j], ahc, bh[j]);
#pragma unroll
        for (int j = 0; j < 8; j++) MMAB(acc[j], alc, bh[j]);
#pragma unroll
        for (int j = 0; j < 8; j++) MMAB(acc[j], ahc, bl[j]);
        if ((kt & 15) == 15 && kc < 2) {
            __syncthreads();
            if (tid == 0) {
                uint32_t mbk = (kc & 1) ? mb1 : mb0;
                uint32_t slot = smem_u32(sb + (kc & 1) * 65536);
                MBAR_EXPECT(mbk, 65536);
                bulk_g2s(slot, Bbase + (kc + 2) * 32768, 32768, mbk);
                bulk_g2s(slot + 32768, Bbase + 524288 + (kc + 2) * 32768, 32768, mbk);
            }
        }
        ahc = ahn; alc = aln;
    }
    int r0 = mb * 128 + w * 16 + (lane >> 2);
#pragma unroll
    for (int j = 0; j < 8; j++) {
        int col = nb * 64 + j * 8 + (lane & 3) * 2;
        float y[4] = { acc[j][0] + bp[col], acc[j][1] + bp[col + 1],
                       acc[j][2] + bp[col], acc[j][3] + bp[col + 1] };
        int rows[4] = { r0, r0, r0 + 8, r0 + 8 };
        int cols[4] = { col, col + 1, col, col + 1 };
#pragma unroll
        for (int q = 0; q < 4; q++)
            *(__half*)(g_Yh + afrag_off(rows[q], cols[q])) = __float2half(y[q]);
    }
}

// ------------------------------ persistent scan (fp16, bulk-staged) -------
__global__ void __launch_bounds__(512) k_scan(
        const float* __restrict__ b0,  const float* __restrict__ gh0,
        const float* __restrict__ gc0, const float* __restrict__ bc0,
        const float* __restrict__ b1,  const float* __restrict__ gx1,
        const float* __restrict__ gh1, const float* __restrict__ gc1,
        const float* __restrict__ bc1) {
    extern __shared__ __align__(16) unsigned char sm[];
    float (*Cs)[65] = (float(*)[65])sm;            // raw gate pre-acts (aliases staging)
    float* psA  = (float*)(sm + 131072);           // 512
    float* ps2A = psA + 512;                       // 512
    float* mcA  = ps2A + 512;                      // 32
    float* rsA  = mcA + 32;                        // 32
    float* prS  = rsA + 32;                        // 256
    float* pqS  = prS + 256;                       // 256
    float* mS   = pqS + 256;                       // 128
    float* sS   = mS + 128;                        // 128
    __shared__ __align__(8) unsigned long long mbar[2];

    const int tid = threadIdx.x, wid = tid >> 5, lane = tid & 31;
    const bool isL1 = blockIdx.x >= 32;
    const int c = isL1 ? (int)blockIdx.x - 32 : (int)blockIdx.x;
    const uint32_t mb0 = smem_u32(&mbar[0]), mb1 = smem_u32(&mbar[1]);

    if (tid == 0) { MBAR_INIT(mb0, 1); MBAR_INIT(mb1, 1); }
    __syncthreads();
    int ph0 = 0, ph1 = 0;

    float creg[4] = {0.f, 0.f, 0.f, 0.f};

    for (int t = 0; t <= Tn; t++) {
        if (!isL1 && t < Tn) {
            const int u = t;
            const unsigned char* Ah = g_W0f + (size_t)c * 262144;
            const unsigned char* Bg = g_h0B[u & 1];
            const int mt = wid & 7, nh = wid >> 3;
            if (tid == 0) {
                MBAR_EXPECT(mb0, 65536);
                bulk_g2s(smem_u32(sm), Bg, 65536, mb0);
                MBAR_EXPECT(mb1, 65536);
                bulk_g2s(smem_u32(sm + 65536), Bg + 65536, 65536, mb1);
            }
            uint4 ahc = *(const uint4*)(Ah + ((size_t)mt << 9) + lane * 16);
            float acc[4][4] = {};
            for (int kt = 0; kt < 64; kt++) {
                if (kt == 0) { MBAR_WAIT(mb0, (uint32_t)(ph0 & 1)); ph0++; }
                if (kt == 32) { MBAR_WAIT(mb1, (uint32_t)(ph1 & 1)); ph1++; }
                uint4 ahn;
                if (kt < 63)
                    ahn = *(const uint4*)(Ah + ((size_t)((kt + 1) * 8 + mt) << 9) + lane * 16);
                const unsigned char* bb = sm + (kt << 11) + (nh << 10);
                uint2 bh[4];
#pragma unroll
                for (int j = 0; j < 4; j++)
                    bh[j] = *(const uint2*)(bb + (j << 8) + lane * 8);
#pragma unroll
                for (int j = 0; j < 4; j++) MMAH(acc[j], ahc, bh[j]);
                ahc = ahn;
            }
            __syncthreads();
            // ---------------- epilogue L0 ----------------
            float s0 = 0.f, q0 = 0.f, s1 = 0.f, q1 = 0.f;
            int r0 = mt * 16 + (lane >> 2);
#pragma unroll
            for (int j = 0; j < 4; j++) {
                int cl = (nh * 4 + j) * 8 + (lane & 3) * 2;
                Cs[r0][cl] = acc[j][0]; Cs[r0][cl + 1] = acc[j][1];
                Cs[r0 + 8][cl] = acc[j][2]; Cs[r0 + 8][cl + 1] = acc[j][3];
                s0 += acc[j][0] + acc[j][1];
                q0 += acc[j][0] * acc[j][0] + acc[j][1] * acc[j][1];
                s1 += acc[j][2] + acc[j][3];
                q1 += acc[j][2] * acc[j][2] + acc[j][3] * acc[j][3];
            }
            s0 += __shfl_xor_sync(0xffffffffu, s0, 1); s0 += __shfl_xor_sync(0xffffffffu, s0, 2);
            q0 += __shfl_xor_sync(0xffffffffu, q0, 1); q0 += __shfl_xor_sync(0xffffffffu, q0, 2);
            s1 += __shfl_xor_sync(0xffffffffu, s1, 1); s1 += __shfl_xor_sync(0xffffffffu, s1, 2);
            q1 += __shfl_xor_sync(0xffffffffu, q1, 1); q1 += __shfl_xor_sync(0xffffffffu, q1, 2);
            if ((lane & 3) == 0) {
                prS[r0 * 2 + nh] = s0; pqS[r0 * 2 + nh] = q0;
                prS[(r0 + 8) * 2 + nh] = s1; pqS[(r0 + 8) * 2 + nh] = q1;
            }
            __syncthreads();
            if (tid < 128) {
                float s = prS[tid * 2] + prS[tid * 2 + 1];
                float q = pqS[tid * 2] + pqS[tid * 2 + 1];
                float m = s * (1.f / 64.f);
                float var = fmaxf(q * (1.f / 64.f) - m * m, 0.f);
                float gam = gh0[(tid >> 5) * Hn + c * 32 + (tid & 31)];
                mS[tid] = m; sS[tid] = gam * rsqrtf(var + 1e-5f);
            }
            __syncthreads();
            int hcl = tid & 31, bg = tid >> 5;
            int hc = c * 32 + hcl;
            float m0 = mS[hcl], c0s = sS[hcl];
            float m1 = mS[32 + hcl], c1s = sS[32 + hcl];
            float m2 = mS[64 + hcl], c2s = sS[64 + hcl];
            float m3 = mS[96 + hcl], c3s = sS[96 + hcl];
            float ov[4], ps = 0.f, p2 = 0.f;
            float bI = b0[hc], bJ = b0[Hn + hc], bF = b0[2 * Hn + hc], bO = b0[3 * Hn + hc];
#pragma unroll
            for (int i = 0; i < 4; i++) {
                int b_ = bg * 4 + i;
                const float* gx = g_GX0 + (size_t)(u * 64 + b_) * FH;
                float preI = (Cs[hcl][b_] - m0) * c0s       + gx[hc]          + bI;
                float preJ = (Cs[32 + hcl][b_] - m1) * c1s  + gx[Hn + hc]     + bJ;
                float preF = (Cs[64 + hcl][b_] - m2) * c2s  + gx[2 * Hn + hc] + bF;
                float preO = (Cs[96 + hcl][b_] - m3) * c3s  + gx[3 * Hn + hc] + bO;
                float cn = sigm(preF + 1.f) * creg[i] + sigm(preI) * tanhf(preJ);
                creg[i] = cn; ov[i] = preO; ps += cn; p2 += cn * cn;
            }
            psA[bg * 32 + hcl] = ps; ps2A[bg * 32 + hcl] = p2;
            __syncthreads();
            if (tid < 32) {
                float s = 0.f, s2 = 0.f;
#pragma unroll
                for (int g = 0; g < 16; g++) { s += psA[g * 32 + tid]; s2 += ps2A[g * 32 + tid]; }
                float m = s * (1.f / 64.f);
                float var = fmaxf(s2 * (1.f / 64.f) - m * m, 0.f);
                mcA[tid] = m; rsA[tid] = rsqrtf(var + 1e-5f);
            }
            __syncthreads();
            float gcv = gc0[hc], bcv = bc0[hc], mm = mcA[hcl], rr = rsA[hcl];
            unsigned char* hb = g_h0B[(u + 1) & 1];
#pragma unroll
            for (int i = 0; i < 4; i++) {
                float cn = gcv * (creg[i] - mm) * rr + bcv;
                float h = sigm(ov[i]) * tanhf(cn);
                write_hfrag(hb, bg * 4 + i, hc, h);
            }
        } else if (isL1 && t >= 1) {
            const int u = t - 1;
            const int g = wid >> 3, mt = (wid >> 1) & 3, nh = wid & 1;
            const unsigned char* Ag = (g == 0 ? g_W1xf : g_W1hf) + (size_t)c * 131072;
            const unsigned char* Bi0 = g_h0B[(u + 1) & 1];
            const unsigned char* Bi1 = g_h1B[u & 1];
            const int gsel = g * 32768;
            if (tid == 0) {
#pragma unroll
                for (int k0 = 0; k0 < 2; k0++) {
                    uint32_t mbk = k0 ? mb1 : mb0;
                    uint32_t slot = smem_u32(sm + k0 * 65536);
                    MBAR_EXPECT(mbk, 65536);
                    bulk_g2s(slot, Bi0 + k0 * 32768, 32768, mbk);
                    bulk_g2s(slot + 32768, Bi1 + k0 * 32768, 32768, mbk);
                }
            }
            uint4 ahc = *(const uint4*)(Ag + ((size_t)mt << 9) + lane * 16);
            float acc[4][4] = {};
            for (int kt = 0; kt < 64; kt++) {
                int kc = kt >> 4;
                if ((kt & 15) == 0) {
                    if (kc & 1) { MBAR_WAIT(mb1, (uint32_t)(ph1 & 1)); ph1++; }
                    else        { MBAR_WAIT(mb0, (uint32_t)(ph0 & 1)); ph0++; }
                }
                uint4 ahn;
                if (kt < 63)
                    ahn = *(const uint4*)(Ag + ((size_t)((kt + 1) * 4 + mt) << 9) + lane * 16);
                const unsigned char* bb = sm + (kc & 1) * 65536 + gsel + ((kt & 15) << 11) + (nh << 10);
                uint2 bh[4];
#pragma unroll
                for (int j = 0; j < 4; j++)
                    bh[j] = *(const uint2*)(bb + (j << 8) + lane * 8);
#pragma unroll
                for (int j = 0; j < 4; j++) MMAH(acc[j], ahc, bh[j]);
                if ((kt & 15) == 15 && kc < 2) {
                    __syncthreads();
                    if (tid == 0) {
                        uint32_t mbk = (kc & 1) ? mb1 : mb0;
                        uint32_t slot = smem_u32(sm + (kc & 1) * 65536);
                        MBAR_EXPECT(mbk, 65536);
                        bulk_g2s(slot, Bi0 + (kc + 2) * 32768, 32768, mbk);
                        bulk_g2s(slot + 32768, Bi1 + (kc + 2) * 32768, 32768, mbk);
                    }
                }
                ahc = ahn;
            }
            __syncthreads();
            // ---------------- epilogue L1 ----------------
            float s0 = 0.f, q0 = 0.f, s1 = 0.f, q1 = 0.f;
            int r0 = g * 64 + mt * 16 + (lane >> 2);
#pragma unroll
            for (int j = 0; j < 4; j++) {
                int cl = (nh * 4 + j) * 8 + (lane & 3) * 2;
                Cs[r0][cl] = acc[j][0]; Cs[r0][cl + 1] = acc[j][1];
                Cs[r0 + 8][cl] = acc[j][2]; Cs[r0 + 8][cl + 1] = acc[j][3];
                s0 += acc[j][0] + acc[j][1];
                q0 += acc[j][0] * acc[j][0] + acc[j][1] * acc[j][1];
                s1 += acc[j][2] + acc[j][3];
                q1 += acc[j][2] * acc[j][2] + acc[j][3] * acc[j][3];
            }
            s0 += __shfl_xor_sync(0xffffffffu, s0, 1); s0 += __shfl_xor_sync(0xffffffffu, s0, 2);
            q0 += __shfl_xor_sync(0xffffffffu, q0, 1); q0 += __shfl_xor_sync(0xffffffffu, q0, 2);
            s1 += __shfl_xor_sync(0xffffffffu, s1, 1); s1 += __shfl_xor_sync(0xffffffffu, s1, 2);
            q1 += __shfl_xor_sync(0xffffffffu, q1, 1); q1 += __shfl_xor_sync(0xffffffffu, q1, 2);
            if ((lane & 3) == 0) {
                prS[r0 * 2 + nh] = s0; pqS[r0 * 2 + nh] = q0;
                prS[(r0 + 8) * 2 + nh] = s1; pqS[(r0 + 8) * 2 + nh] = q1;
            }
            __syncthreads();
            if (tid < 128) {
                float s = prS[tid * 2] + prS[tid * 2 + 1];
                float q = pqS[tid * 2] + pqS[tid * 2 + 1];
                float m = s * (1.f / 64.f);
                float var = fmaxf(q * (1.f / 64.f) - m * m, 0.f);
                int rr_ = tid & 63;
                int gi = (rr_ >> 4) * Hn + c * 16 + (rr_ & 15);
                float gam = (tid < 64) ? gx1[gi] : gh1[gi];
                mS[tid] = m; sS[tid] = gam * rsqrtf(var + 1e-5f);
            }
            __syncthreads();
            int hcl = tid & 15, bg = tid >> 4;
            int hc = c * 16 + hcl;
            float ov[2], ps = 0.f, p2 = 0.f;
            float bI = b1[hc], bJ = b1[Hn + hc], bF = b1[2 * Hn + hc], bO = b1[3 * Hn + hc];
#pragma unroll
            for (int i = 0; i < 2; i++) {
                int b_ = bg * 2 + i;
                float preI = (Cs[hcl][b_] - mS[hcl]) * sS[hcl]
                           + (Cs[64 + hcl][b_] - mS[64 + hcl]) * sS[64 + hcl] + bI;
                float preJ = (Cs[16 + hcl][b_] - mS[16 + hcl]) * sS[16 + hcl]
                           + (Cs[80 + hcl][b_] - mS[80 + hcl]) * sS[80 + hcl] + bJ;
                float preF = (Cs[32 + hcl][b_] - mS[32 + hcl]) * sS[32 + hcl]
                           + (Cs[96 + hcl][b_] - mS[96 + hcl]) * sS[96 + hcl] + bF;
                float preO = (Cs[48 + hcl][b_] - mS[48 + hcl]) * sS[48 + hcl]
                           + (Cs[112 + hcl][b_] - mS[112 + hcl]) * sS[112 + hcl] + bO;
                float cn = sigm(preF + 1.f) * creg[i] + sigm(preI) * tanhf(preJ);
                creg[i] = cn; ov[i] = preO; ps += cn; p2 += cn * cn;
            }
            psA[bg * 16 + hcl] = ps; ps2A[bg * 16 + hcl] = p2;
            __syncthreads();
            if (tid < 16) {
                float s = 0.f, s2 = 0.f;
#pragma unroll
                for (int gg = 0; gg < 32; gg++) { s += psA[gg * 16 + tid]; s2 += ps2A[gg * 16 + tid]; }
                float m = s * (1.f / 64.f);
                float var = fmaxf(s2 * (1.f / 64.f) - m * m, 0.f);
                mcA[tid] = m; rsA[tid] = rsqrtf(var + 1e-5f);
            }
            __syncthreads();
            float gcv = gc1[hc], bcv = bc1[hc], mm = mcA[hcl], rr = rsA[hcl];
            unsigned char* hb = g_h1B[(u + 1) & 1];
#pragma unroll
            for (int i = 0; i < 2; i++) {
                int b_ = bg * 2 + i;
                float cn = gcv * (creg[i] - mm) * rr + bcv;
                float h = sigm(ov[i]) * tanhf(cn);
                write_hfrag(hb, b_, hc, h);
                __nv_bfloat16 hhi = __float2bfloat16(h);
                __nv_bfloat16 hlo = __float2bfloat16(h - __bfloat162float(hhi));
                size_t off = afrag_off1k(b_ * Tn + u, hc);
                *(__nv_bfloat16*)(g_Hf + off) = hhi;
                *(__nv_bfloat16*)(g_Hf + HPLANE + off) = hlo;
            }
        }
        grid_bar();
    }
}

// ------------------------------ launch ------------------------------------
extern "C" void kernel_launch(void* const* d_in, const int* in_sizes, int n_in,
                              void* d_out, int out_size) {
    const int*   inp = (const int*)  d_in[0];
    const float* emb = (const float*)d_in[1];
    const float* Wx0 = (const float*)d_in[2];
    const float* Wh0 = (const float*)d_in[3];
    const float* b0  = (const float*)d_in[4];
    const float* gx0 = (const float*)d_in[5];
    const float* gh0 = (const float*)d_in[6];
    const float* gc0 = (const float*)d_in[7];
    const float* bc0 = (const float*)d_in[8];
    const float* Wx1 = (const float*)d_in[9];
    const float* Wh1 = (const float*)d_in[10];
    const float* b1  = (const float*)d_in[11];
    const float* gx1 = (const float*)d_in[12];
    const float* gh1 = (const float*)d_in[13];
    const float* gc1 = (const float*)d_in[14];
    const float* bc1 = (const float*)d_in[15];
    const float* Wp  = (const float*)d_in[16];
    const float* bp  = (const float*)d_in[17];
    const float* sw  = (const float*)d_in[18];
    const float* sb  = (const float*)d_in[19];
    float* out = (float*)d_out;

    unsigned char *pXf, *pWx0B;
    cudaGetSymbolAddress((void**)&pXf,  g_Xf);
    cudaGetSymbolAddress((void**)&pWx0B, g_Wx0B);

    cudaFuncSetAttribute(k_scan, cudaFuncAttributeMaxDynamicSharedMemorySize, 138496);
    cudaFuncSetAttribute(k_gemm_gx0, cudaFuncAttributeMaxDynamicSharedMemorySize, 65536);
    cudaFuncSetAttribute(k_gemm_wp, cudaFuncAttributeMaxDynamicSharedMemorySize, 131072);
    cudaFuncSetAttribute(k_gemm_logits, cudaFuncAttributeMaxDynamicSharedMemorySize, 32768);

    k_embed<<<Tn * Bn, 256>>>(inp, emb);
    k_prepw<<<dim3(16384, 3), 256>>>(Wh0, Wx1, Wh1);
    k_prepB<<<(NUn * (FH + Vn)) / 256, 256>>>(Wx0, sw);
    k_prepWp<<<(Hn * NUn) / 256, 256>>>(Wp);
    k_gemm_gx0<<<dim3(FH / 64, 64), 256, 65536>>>(pXf, pWx0B, gx0);
    k_scan<<<NBLK, 512, 138496>>>(b0, gh0, gc0, bc0, b1, gx1, gh1, gc1, bc1);
    k_gemm_wp<<<dim3(NUn / 64, 64), 256, 131072>>>(bp);
    k_gemm_logits<<<dim3(Vn / 64, 64), 256, 32768>>>(sb, out);
}

// round 16
// speedup vs baseline: 1.3723x; 1.0347x over previous
#include <cuda_runtime.h>
#include <cuda_bf16.h>
#include <cuda_fp16.h>
#include <cstdint>
#include <math.h>

#define Tn   128
#define Bn   64
#define Hn   1024
#define NUn  256
#define Vn   8000
#define FH   4096
#define NBLK 96
#define APLANE 4194304    // 8192*512: one plane of a K=256 A-frag image
#define HPLANE 16777216   // 8192*2048: one plane of the K=1024 H1 A-frag image

// ------------------------------ device scratch ----------------------------
__device__ float g_GX0[Tn * Bn * FH];     // BN(x@Wx0) with gx0 folded

// scan weights: A-fragment images, SINGLE fp16 plane per CTA slice
__device__ __align__(16) unsigned char g_W0f [32 * 262144];
__device__ __align__(16) unsigned char g_W1xf[64 * 131072];
__device__ __align__(16) unsigned char g_W1hf[64 * 131072];
// h states as B-fragment images, single fp16 plane: [parity][128KB]
__device__ __align__(16) unsigned char g_h0B[2][131072];
__device__ __align__(16) unsigned char g_h1B[2][131072];
// A-frag images
__device__ __align__(16) unsigned char g_Xf[2 * APLANE];   // X, K=256, bf16 hi|lo
__device__ __align__(16) unsigned char g_Yh[APLANE];       // Y, K=256, fp16 single
__device__ __align__(16) unsigned char g_Hf[2 * HPLANE];   // H1, K=1024, bf16 hi|lo
// B-frag images
__device__ __align__(16) unsigned char g_Wx0B[2 * 4096 * 512];  // bf16 hi|lo
__device__ __align__(16) unsigned char g_swH [8000 * 512];      // fp16 single
__device__ __align__(16) unsigned char g_WpB [2 * 4 * 131072];  // bf16 hi|lo

__device__ unsigned g_barCnt;
__device__ volatile unsigned g_barGen;

__device__ __forceinline__ float sigm(float x) { return __fdividef(1.f, 1.f + __expf(-x)); }

#define MMAB(c, a, b) \
    asm volatile("mma.sync.aligned.m16n8k16.row.col.f32.bf16.bf16.f32 " \
        "{%0,%1,%2,%3},{%4,%5,%6,%7},{%8,%9},{%0,%1,%2,%3};" \
        : "+f"((c)[0]), "+f"((c)[1]), "+f"((c)[2]), "+f"((c)[3]) \
        : "r"((a).x), "r"((a).y), "r"((a).z), "r"((a).w), "r"((b).x), "r"((b).y))
#define MMAH(c, a, b) \
    asm volatile("mma.sync.aligned.m16n8k16.row.col.f32.f16.f16.f32 " \
        "{%0,%1,%2,%3},{%4,%5,%6,%7},{%8,%9},{%0,%1,%2,%3};" \
        : "+f"((c)[0]), "+f"((c)[1]), "+f"((c)[2]), "+f"((c)[3]) \
        : "r"((a).x), "r"((a).y), "r"((a).z), "r"((a).w), "r"((b).x), "r"((b).y))

__device__ __forceinline__ uint32_t smem_u32(const void* p) {
    uint32_t a;
    asm("{ .reg .u64 t; cvta.to.shared.u64 t, %1; cvt.u32.u64 %0, t; }" : "=r"(a) : "l"(p));
    return a;
}
__device__ __forceinline__ void cpa16(uint32_t dst, const void* src) {
    asm volatile("cp.async.cg.shared.global [%0], [%1], 16;" :: "r"(dst), "l"(src) : "memory");
}
#define CP_COMMIT() asm volatile("cp.async.commit_group;" ::: "memory")
#define CP_WAIT(n)  asm volatile("cp.async.wait_group %0;" :: "n"(n) : "memory")

__device__ __forceinline__ void bulk_g2s(uint32_t dst, const void* src, uint32_t bytes, uint32_t mbar) {
    asm volatile(
        "cp.async.bulk.shared::cluster.global.mbarrier::complete_tx::bytes [%0], [%1], %2, [%3];"
        :: "r"(dst), "l"(src), "r"(bytes), "r"(mbar) : "memory");
}
#define MBAR_INIT(a, n) \
    asm volatile("mbarrier.init.shared.b64 [%0], %1;" :: "r"(a), "r"((uint32_t)(n)) : "memory")
#define MBAR_EXPECT(a, n) \
    asm volatile("mbarrier.arrive.expect_tx.shared.b64 _, [%0], %1;" :: "r"(a), "r"((uint32_t)(n)) : "memory")
#define MBAR_WAIT(a, ph) do {                                                  \
    uint32_t _m = (a), _p = (ph), _d;                                          \
    asm volatile("{\n\t.reg .pred p;\n\t"                                      \
        "mbarrier.try_wait.parity.acquire.cta.shared::cta.b64 p, [%1], %2;\n\t"\
        "selp.b32 %0, 1, 0, p;\n\t}"                                           \
        : "=r"(_d) : "r"(_m), "r"(_p) : "memory");                             \
    if (!_d) {                                                                 \
        asm volatile("{\n\t.reg .pred P1;\n\t"                                 \
            "W_%=:\n\t"                                                        \
            "mbarrier.try_wait.parity.acquire.cta.shared::cta.b64 P1, [%0], %1, 0x989680;\n\t" \
            "@P1 bra.uni D_%=;\n\tbra.uni W_%=;\n\tD_%=:\n\t}"                 \
            :: "r"(_m), "r"(_p) : "memory");                                   \
    }                                                                          \
} while (0)

__device__ __forceinline__ void grid_bar() {
    __syncthreads();
    if (threadIdx.x == 0) {
        unsigned gen = g_barGen;
        __threadfence();
        if (atomicAdd(&g_barCnt, 1u) == NBLK - 1) {
            g_barCnt = 0;
            __threadfence();
            g_barGen = gen + 1;
        } else {
            while (g_barGen == gen) { __nanosleep(64); }
        }
        __threadfence();
    }
    __syncthreads();
}

// A-fragment offset, K=256 image
__device__ __forceinline__ size_t afrag_off(int m, int k) {
    int mt = m >> 4, mi = m & 15, kt = k >> 4, ki = k & 15;
    int lane = (mi & 7) * 4 + ((ki & 7) >> 1);
    int reg  = (mi >> 3) + ((ki >> 3) << 1);
    return ((size_t)(mt * 16 + kt) << 9) + lane * 16 + (reg << 2) + ((ki & 1) << 1);
}
// A-fragment offset, K=1024 image
__device__ __forceinline__ size_t afrag_off1k(int m, int k) {
    int mt = m >> 4, mi = m & 15, kt = k >> 4, ki = k & 15;
    int lane = (mi & 7) * 4 + ((ki & 7) >> 1);
    int reg  = (mi >> 3) + ((ki >> 3) << 1);
    return ((size_t)(mt * 64 + kt) << 9) + lane * 16 + (reg << 2) + ((ki & 1) << 1);
}
// B-fragment offset, K=256 image (ntile-major)
__device__ __forceinline__ size_t bfrag_off(int k, int n) {
    int nt = n >> 3, ni = n & 7, kt = k >> 4, ki = k & 15;
    int ln = ni * 4 + ((ki & 7) >> 1);
    return ((size_t)(nt * 16 + kt) << 8) + ln * 8 + ((ki >> 3) << 2) + ((ki & 1) << 1);
}

// write one h value into the scan B-frag plane (kt-major tiles, K=1024), fp16
__device__ __forceinline__ void write_hfrag(unsigned char* hb, int b, int hc, float h) {
    int kt = hc >> 4, nt = b >> 3, ki = hc & 15, ni = b & 7;
    int ln = ni * 4 + ((ki & 7) >> 1);
    int off = ((kt * 8 + nt) << 8) + ln * 8 + ((ki >> 3) << 2) + ((ki & 1) << 1);
    *(__half*)(hb + off) = __float2half(h);
}

// ------------------------------ embedding + state init --------------------
__global__ void k_embed(const int* __restrict__ inp, const float* __restrict__ emb) {
    int row = blockIdx.x;                 // t*64 + b
    int u = threadIdx.x;
    int i = blockIdx.x * 256 + threadIdx.x;
    if (i < 65536) ((uint32_t*)g_h0B)[i] = 0u;
    else if (i < 131072) ((uint32_t*)g_h1B)[i - 65536] = 0u;
    int t = row >> 6, b = row & 63;
    float v = emb[(size_t)inp[b * Tn + t] * NUn + u];
    __nv_bfloat16 hi = __float2bfloat16(v);
    __nv_bfloat16 lo = __float2bfloat16(v - __bfloat162float(hi));
    size_t off = afrag_off(row, u);
    *(__nv_bfloat16*)(g_Xf + off) = hi;
    *(__nv_bfloat16*)(g_Xf + APLANE + off) = lo;
}

// ------------------------------ weights -> B-frags ------------------------
__global__ void k_prepB(const float* __restrict__ Wx0, const float* __restrict__ sw) {
    int idx = blockIdx.x * 256 + threadIdx.x;
    if (idx < NUn * FH) {
        int k = idx / FH, n = idx - k * FH;
        float v = Wx0[idx];
        __nv_bfloat16 hi = __float2bfloat16(v);
        __nv_bfloat16 lo = __float2bfloat16(v - __bfloat162float(hi));
        size_t off = bfrag_off(k, n);
        *(__nv_bfloat16*)(g_Wx0B + off) = hi;
        *(__nv_bfloat16*)(g_Wx0B + (size_t)FH * 512 + off) = lo;
    } else {
        int local = idx - NUn * FH;
        int k = local / Vn, n = local - k * Vn;
        *(__half*)(g_swH + bfrag_off(k, n)) = __float2half(sw[local]);
    }
}

// ------------------------------ Wp -> B-frags (K=1024, chunk-contiguous) --
__global__ void k_prepWp(const float* __restrict__ Wp) {
    int idx = blockIdx.x * 256 + threadIdx.x;   // k*256 + n
    int k = idx >> 8, n = idx & 255;
    float v = Wp[idx];
    __nv_bfloat16 hi = __float2bfloat16(v);
    __nv_bfloat16 lo = __float2bfloat16(v - __bfloat162float(hi));
    int nb = n >> 6, ntl = (n >> 3) & 7, ni = n & 7;
    int kt = k >> 4, ki = k & 15;
    int ln = ni * 4 + ((ki & 7) >> 1);
    size_t off = (size_t)nb * 131072 + ((size_t)(kt * 8 + ntl) << 8)
               + ln * 8 + ((ki >> 3) << 2) + ((ki & 1) << 1);
    *(__nv_bfloat16*)(g_WpB + off) = hi;
    *(__nv_bfloat16*)(g_WpB + 524288 + off) = lo;
}

// ------------------------------ scan weight prep (single fp16) ------------
__global__ void k_prepw(const float* __restrict__ Wh0, const float* __restrict__ Wx1,
                        const float* __restrict__ Wh1) {
    int which = blockIdx.y;
    const float* W = which == 0 ? Wh0 : (which == 1 ? Wx1 : Wh1);
    int idx = blockIdx.x * 256 + threadIdx.x;   // k*4096 + gcol
    int k = idx >> 12, gcol = idx & 4095;
    __half hv = __float2half(W[idx]);
    int g = gcol >> 10, hc = gcol & 1023;
    unsigned char* base;
    int MT, m;
    if (which == 0) {
        int c = hc >> 5; m = g * 32 + (hc & 31); MT = 8;
        base = g_W0f + (size_t)c * 262144;
    } else {
        int c = hc >> 4; m = g * 16 + (hc & 15); MT = 4;
        base = (which == 1 ? g_W1xf : g_W1hf) + (size_t)c * 131072;
    }
    int kt = k >> 4, ki = k & 15, mt = m >> 4, mi = m & 15;
    int lane = (mi & 7) * 4 + ((ki & 7) >> 1);
    int reg  = (mi >> 3) + ((ki >> 3) << 1);
    int off  = ((kt * MT + mt) << 9) + lane * 16 + (reg << 2) + ((ki & 1) << 1);
    *(__half*)(base + off) = hv;
}

// ------------------------------ GX0 MMA with fused per-timestep BN --------
__global__ void __launch_bounds__(256) k_gemm_gx0(
        const unsigned char* __restrict__ Af, const unsigned char* __restrict__ Bf,
        const float* __restrict__ gx0) {
    extern __shared__ unsigned char sb[];
    const int tid = threadIdx.x, w = tid >> 5, lane = tid & 31;
    const int nb = blockIdx.x, mb = blockIdx.y;
    {
        int p = tid >> 7, o = (tid & 127) * 16;
        const unsigned char* src = Bf + (size_t)p * ((size_t)FH * 512) + (size_t)nb * 32768 + o;
        uint32_t dst = smem_u32(sb + p * 32768 + o);
#pragma unroll
        for (int i = 0; i < 16; i++) cpa16(dst + i * 2048, src + i * 2048);
        CP_COMMIT(); CP_WAIT(0);
    }
    __syncthreads();
    const size_t abase = ((size_t)(mb * 8 + w) << 13) + lane * 16;
    uint4 ahc = *(const uint4*)(Af + abase);
    uint4 alc = *(const uint4*)(Af + APLANE + abase);
    float acc[8][4] = {};
#pragma unroll
    for (int kt = 0; kt < 16; kt++) {
        uint4 ahn, aln;
        if (kt < 15) {
            ahn = *(const uint4*)(Af + abase + (kt + 1) * 512);
            aln = *(const uint4*)(Af + APLANE + abase + (kt + 1) * 512);
        }
        uint2 bh[8], bl[8];
#pragma unroll
        for (int j = 0; j < 8; j++) {
            bh[j] = *(const uint2*)(sb + (j * 16 + kt) * 256 + lane * 8);
            bl[j] = *(const uint2*)(sb + 32768 + (j * 16 + kt) * 256 + lane * 8);
        }
#pragma unroll
        for (int j = 0; j < 8; j++) MMAB(acc[j], ahc, bh[j]);
#pragma unroll
        for (int j = 0; j < 8; j++) MMAB(acc[j], alc, bh[j]);
#pragma unroll
        for (int j = 0; j < 8; j++) MMAB(acc[j], ahc, bl[j]);
        ahc = ahn; alc = aln;
    }
    __syncthreads();
    float (*Cs)[65] = (float(*)[65])sb;
    float* mS = (float*)(sb + 33280);
    float* sS = (float*)(sb + 33792);
    int r0 = w * 16 + (lane >> 2);
#pragma unroll
    for (int j = 0; j < 8; j++) {
        int cl = j * 8 + (lane & 3) * 2;
        Cs[r0][cl] = acc[j][0]; Cs[r0][cl + 1] = acc[j][1];
        Cs[r0 + 8][cl] = acc[j][2]; Cs[r0 + 8][cl + 1] = acc[j][3];
    }
    __syncthreads();
    if (tid < 128) {
        int half = tid >> 6, col = tid & 63;
        float s = 0.f, s2 = 0.f;
#pragma unroll
        for (int b = 0; b < 64; b++) {
            float v = Cs[half * 64 + b][col];
            s += v; s2 += v * v;
        }
        float m = s * (1.f / 64.f);
        float var = fmaxf(s2 * (1.f / 64.f) - m * m, 0.f);
        mS[tid] = m;
        sS[tid] = gx0[nb * 64 + col] * rsqrtf(var + 1e-5f);
    }
    __syncthreads();
    {
        int col = tid & 63, seg = tid >> 6;
#pragma unroll
        for (int i = 0; i < 32; i++) {
            int rr = seg * 32 + i;
            int sidx = (rr >> 6) * 64 + col;
            g_GX0[(size_t)(mb * 128 + rr) * FH + nb * 64 + col] =
                sS[sidx] * (Cs[rr][col] - mS[sidx]);
        }
    }
}

// ------------------------------ logits MMA GEMM, K=256 (fp16, 1-product) --
__global__ void __launch_bounds__(256) k_gemm_logits(
        const float* __restrict__ bias, float* __restrict__ C) {
    extern __shared__ unsigned char sb[];
    const int tid = threadIdx.x, w = tid >> 5, lane = tid & 31;
    const int nb = blockIdx.x, mb = blockIdx.y;
    {
        int o = tid * 16;
        const unsigned char* src = g_swH + (size_t)nb * 32768 + o;
        uint32_t dst = smem_u32(sb + o);
#pragma unroll
        for (int i = 0; i < 8; i++) cpa16(dst + i * 4096, src + i * 4096);
        CP_COMMIT(); CP_WAIT(0);
    }
    __syncthreads();
    const size_t abase = ((size_t)(mb * 8 + w) << 13) + lane * 16;
    uint4 ac = *(const uint4*)(g_Yh + abase);
    float acc[8][4] = {};
#pragma unroll
    for (int kt = 0; kt < 16; kt++) {
        uint4 an;
        if (kt < 15) an = *(const uint4*)(g_Yh + abase + (kt + 1) * 512);
        uint2 bh[8];
#pragma unroll
        for (int j = 0; j < 8; j++)
            bh[j] = *(const uint2*)(sb + (j * 16 + kt) * 256 + lane * 8);
#pragma unroll
        for (int j = 0; j < 8; j++) MMAH(acc[j], ac, bh[j]);
        ac = an;
    }
    int r0 = mb * 128 + w * 16 + (lane >> 2);
#pragma unroll
    for (int j = 0; j < 8; j++) {
        int col = nb * 64 + j * 8 + (lane & 3) * 2;
        float b0v = bias[col], b1v = bias[col + 1];
        *(float2*)(C + (size_t)r0 * Vn + col) = make_float2(acc[j][0] + b0v, acc[j][1] + b1v);
        *(float2*)(C + (size_t)(r0 + 8) * Vn + col) = make_float2(acc[j][2] + b0v, acc[j][3] + b1v);
    }
}

// ------------------------------ Wp MMA GEMM, K=1024 -----------------------
__global__ void __launch_bounds__(256) k_gemm_wp(const float* __restrict__ bp) {
    extern __shared__ unsigned char sb[];
    __shared__ __align__(8) unsigned long long mbar[2];
    const int tid = threadIdx.x, w = tid >> 5, lane = tid & 31;
    const int nb = blockIdx.x, mb = blockIdx.y;
    const uint32_t mb0 = smem_u32(&mbar[0]), mb1 = smem_u32(&mbar[1]);
    if (tid == 0) { MBAR_INIT(mb0, 1); MBAR_INIT(mb1, 1); }
    __syncthreads();
    const unsigned char* Bbase = g_WpB + (size_t)nb * 131072;
    if (tid == 0) {
#pragma unroll
        for (int k0 = 0; k0 < 2; k0++) {
            uint32_t mbk = k0 ? mb1 : mb0;
            uint32_t slot = smem_u32(sb + k0 * 65536);
            MBAR_EXPECT(mbk, 65536);
            bulk_g2s(slot, Bbase + k0 * 32768, 32768, mbk);
            bulk_g2s(slot + 32768, Bbase + 524288 + k0 * 32768, 32768, mbk);
        }
    }
    const size_t abase = ((size_t)(mb * 8 + w) << 15) + lane * 16;
    int ph0 = 0, ph1 = 0;
    uint4 ahc = *(const uint4*)(g_Hf + abase);
    uint4 alc = *(const uint4*)(g_Hf + HPLANE + abase);
    float acc[8][4] = {};
    for (int kt = 0; kt < 64; kt++) {
        int kc = kt >> 4;
        if ((kt & 15) == 0) {
            if (kc & 1) { MBAR_WAIT(mb1, (uint32_t)(ph1 & 1)); ph1++; }
            else        { MBAR_WAIT(mb0, (uint32_t)(ph0 & 1)); ph0++; }
        }
        uint4 ahn, aln;
        if (kt < 63) {
            ahn = *(const uint4*)(g_Hf + abase + ((size_t)(kt + 1) << 9));
            aln = *(const uint4*)(g_Hf + HPLANE + abase + ((size_t)(kt + 1) << 9));
        }
        const unsigned char* bb = sb + (kc & 1) * 65536 + ((kt & 15) << 11);
        uint2 bh[8], bl[8];
#pragma unroll
        for (int j = 0; j < 8; j++) {
            bh[j] = *(const uint2*)(bb + (j << 8) + lane * 8);
            bl[j] = *(const uint2*)(bb + 32768 + (j << 8) + lane * 8);
        }
#pragma unroll
        for (int j = 0; j < 8; j++) MMAB(acc[j], ahc, bh[j]);
#pragma unroll
        for (int j = 0; j < 8; j++) MMAB(acc[j], alc, bh[j]);
#pragma unroll
        for (int j = 0; j < 8; j++) MMAB(acc[j], ahc, bl[j]);
        if ((kt & 15) == 15 && kc < 2) {
            __syncthreads();
            if (tid == 0) {
                uint32_t mbk = (kc & 1) ? mb1 : mb0;
                uint32_t slot = smem_u32(sb + (kc & 1) * 65536);
                MBAR_EXPECT(mbk, 65536);
                bulk_g2s(slot, Bbase + (kc + 2) * 32768, 32768, mbk);
                bulk_g2s(slot + 32768, Bbase + 524288 + (kc + 2) * 32768, 32768, mbk);
            }
        }
        ahc = ahn; alc = aln;
    }
    int r0 = mb * 128 + w * 16 + (lane >> 2);
#pragma unroll
    for (int j = 0; j < 8; j++) {
        int col = nb * 64 + j * 8 + (lane & 3) * 2;
        float y[4] = { acc[j][0] + bp[col], acc[j][1] + bp[col + 1],
                       acc[j][2] + bp[col], acc[j][3] + bp[col + 1] };
        int rows[4] = { r0, r0, r0 + 8, r0 + 8 };
        int cols[4] = { col, col + 1, col, col + 1 };
#pragma unroll
        for (int q = 0; q < 4; q++)
            *(__half*)(g_Yh + afrag_off(rows[q], cols[q])) = __float2half(y[q]);
    }
}

// ------------------------------ persistent scan (fp16, bulk-staged) -------
__global__ void __launch_bounds__(512) k_scan(
        const float* __restrict__ b0,  const float* __restrict__ gh0,
        const float* __restrict__ gc0, const float* __restrict__ bc0,
        const float* __restrict__ b1,  const float* __restrict__ gx1,
        const float* __restrict__ gh1, const float* __restrict__ gc1,
        const float* __restrict__ bc1) {
    extern __shared__ __align__(16) unsigned char sm[];
    float (*Cs)[65] = (float(*)[65])sm;            // raw gate pre-acts (aliases staging)
    float* psA  = (float*)(sm + 131072);           // 512
    float* ps2A = psA + 512;                       // 512
    float* mcA  = ps2A + 512;                      // 32
    float* rsA  = mcA + 32;                        // 32
    float* prS  = rsA + 32;                        // 256
    float* pqS  = prS + 256;                       // 256
    float* mS   = pqS + 256;                       // 128
    float* sS   = mS + 128;                        // 128
    __shared__ __align__(8) unsigned long long mbar[2];

    const int tid = threadIdx.x, wid = tid >> 5, lane = tid & 31;
    const bool isL1 = blockIdx.x >= 32;
    const int c = isL1 ? (int)blockIdx.x - 32 : (int)blockIdx.x;
    const uint32_t mb0 = smem_u32(&mbar[0]), mb1 = smem_u32(&mbar[1]);

    if (tid == 0) { MBAR_INIT(mb0, 1); MBAR_INIT(mb1, 1); }
    __syncthreads();
    int ph0 = 0, ph1 = 0;

    float creg[4] = {0.f, 0.f, 0.f, 0.f};

    for (int t = 0; t <= Tn; t++) {
        if (!isL1 && t < Tn) {
            const int u = t;
            const unsigned char* Ah = g_W0f + (size_t)c * 262144;
            const unsigned char* Bg = g_h0B[u & 1];
            const int mt = wid & 7, nh = wid >> 3;
            const int hcl = tid & 31, bg = tid >> 5;
            const int hc = c * 32 + hcl;
            if (tid == 0) {
                MBAR_EXPECT(mb0, 65536);
                bulk_g2s(smem_u32(sm), Bg, 65536, mb0);
                MBAR_EXPECT(mb1, 65536);
                bulk_g2s(smem_u32(sm + 65536), Bg + 65536, 65536, mb1);
            }
            // prefetch GX0 gate terms for this step (independent of MMA)
            float gxv[4][4];
#pragma unroll
            for (int i = 0; i < 4; i++) {
                const float* gx = g_GX0 + (size_t)(u * 64 + bg * 4 + i) * FH;
                gxv[i][0] = gx[hc];
                gxv[i][1] = gx[Hn + hc];
                gxv[i][2] = gx[2 * Hn + hc];
                gxv[i][3] = gx[3 * Hn + hc];
            }
            uint4 ahc = *(const uint4*)(Ah + ((size_t)mt << 9) + lane * 16);
            float acc[4][4] = {};
            for (int kt = 0; kt < 64; kt++) {
                if (kt == 0) { MBAR_WAIT(mb0, (uint32_t)(ph0 & 1)); ph0++; }
                if (kt == 32) { MBAR_WAIT(mb1, (uint32_t)(ph1 & 1)); ph1++; }
                uint4 ahn;
                if (kt < 63)
                    ahn = *(const uint4*)(Ah + ((size_t)((kt + 1) * 8 + mt) << 9) + lane * 16);
                const unsigned char* bb = sm + (kt << 11) + (nh << 10);
                uint2 bh[4];
#pragma unroll
                for (int j = 0; j < 4; j++)
                    bh[j] = *(const uint2*)(bb + (j << 8) + lane * 8);
#pragma unroll
                for (int j = 0; j < 4; j++) MMAH(acc[j], ahc, bh[j]);
                ahc = ahn;
            }
            __syncthreads();
            // ---------------- epilogue L0 ----------------
            float s0 = 0.f, q0 = 0.f, s1 = 0.f, q1 = 0.f;
            int r0 = mt * 16 + (lane >> 2);
#pragma unroll
            for (int j = 0; j < 4; j++) {
                int cl = (nh * 4 + j) * 8 + (lane & 3) * 2;
                Cs[r0][cl] = acc[j][0]; Cs[r0][cl + 1] = acc[j][1];
                Cs[r0 + 8][cl] = acc[j][2]; Cs[r0 + 8][cl + 1] = acc[j][3];
                s0 += acc[j][0] + acc[j][1];
                q0 += acc[j][0] * acc[j][0] + acc[j][1] * acc[j][1];
                s1 += acc[j][2] + acc[j][3];
                q1 += acc[j][2] * acc[j][2] + acc[j][3] * acc[j][3];
            }
            s0 += __shfl_xor_sync(0xffffffffu, s0, 1); s0 += __shfl_xor_sync(0xffffffffu, s0, 2);
            q0 += __shfl_xor_sync(0xffffffffu, q0, 1); q0 += __shfl_xor_sync(0xffffffffu, q0, 2);
            s1 += __shfl_xor_sync(0xffffffffu, s1, 1); s1 += __shfl_xor_sync(0xffffffffu, s1, 2);
            q1 += __shfl_xor_sync(0xffffffffu, q1, 1); q1 += __shfl_xor_sync(0xffffffffu, q1, 2);
            if ((lane & 3) == 0) {
                prS[r0 * 2 + nh] = s0; pqS[r0 * 2 + nh] = q0;
                prS[(r0 + 8) * 2 + nh] = s1; pqS[(r0 + 8) * 2 + nh] = q1;
            }
            __syncthreads();
            if (tid < 128) {
                float s = prS[tid * 2] + prS[tid * 2 + 1];
                float q = pqS[tid * 2] + pqS[tid * 2 + 1];
                float m = s * (1.f / 64.f);
                float var = fmaxf(q * (1.f / 64.f) - m * m, 0.f);
                float gam = gh0[(tid >> 5) * Hn + c * 32 + (tid & 31)];
                mS[tid] = m; sS[tid] = gam * rsqrtf(var + 1e-5f);
            }
            __syncthreads();
            float m0 = mS[hcl], c0s = sS[hcl];
            float m1 = mS[32 + hcl], c1s = sS[32 + hcl];
            float m2 = mS[64 + hcl], c2s = sS[64 + hcl];
            float m3 = mS[96 + hcl], c3s = sS[96 + hcl];
            float ov[4], ps = 0.f, p2 = 0.f;
            float bI = b0[hc], bJ = b0[Hn + hc], bF = b0[2 * Hn + hc], bO = b0[3 * Hn + hc];
#pragma unroll
            for (int i = 0; i < 4; i++) {
                int b_ = bg * 4 + i;
                float preI = (Cs[hcl][b_] - m0) * c0s       + gxv[i][0] + bI;
                float preJ = (Cs[32 + hcl][b_] - m1) * c1s  + gxv[i][1] + bJ;
                float preF = (Cs[64 + hcl][b_] - m2) * c2s  + gxv[i][2] + bF;
                float preO = (Cs[96 + hcl][b_] - m3) * c3s  + gxv[i][3] + bO;
                float cn = sigm(preF + 1.f) * creg[i] + sigm(preI) * tanhf(preJ);
                creg[i] = cn; ov[i] = preO; ps += cn; p2 += cn * cn;
            }
            psA[bg * 32 + hcl] = ps; ps2A[bg * 32 + hcl] = p2;
            __syncthreads();
            if (tid < 32) {
                float s = 0.f, s2 = 0.f;
#pragma unroll
                for (int g = 0; g < 16; g++) { s += psA[g * 32 + tid]; s2 += ps2A[g * 32 + tid]; }
                float m = s * (1.f / 64.f);
                float var = fmaxf(s2 * (1.f / 64.f) - m * m, 0.f);
                mcA[tid] = m; rsA[tid] = rsqrtf(var + 1e-5f);
            }
            __syncthreads();
            float gcv = gc0[hc], bcv = bc0[hc], mm = mcA[hcl], rr = rsA[hcl];
            unsigned char* hb = g_h0B[(u + 1) & 1];
#pragma unroll
            for (int i = 0; i < 4; i++) {
                float cn = gcv * (creg[i] - mm) * rr + bcv;
                float h = sigm(ov[i]) * tanhf(cn);
                write_hfrag(hb, bg * 4 + i, hc, h);
            }
        } else if (isL1 && t >= 1) {
            const int u = t - 1;
            const int g = wid >> 3, mt = (wid >> 1) & 3, nh = wid & 1;
            const unsigned char* Ag = (g == 0 ? g_W1xf : g_W1hf) + (size_t)c * 131072;
            const unsigned char* Bi0 = g_h0B[(u + 1) & 1];
            const unsigned char* Bi1 = g_h1B[u & 1];
            const int gsel = g * 32768;
            if (tid == 0) {
#pragma unroll
                for (int k0 = 0; k0 < 2; k0++) {
                    uint32_t mbk = k0 ? mb1 : mb0;
                    uint32_t slot = smem_u32(sm + k0 * 65536);
                    MBAR_EXPECT(mbk, 65536);
                    bulk_g2s(slot, Bi0 + k0 * 32768, 32768, mbk);
                    bulk_g2s(slot + 32768, Bi1 + k0 * 32768, 32768, mbk);
                }
            }
            uint4 ahc = *(const uint4*)(Ag + ((size_t)mt << 9) + lane * 16);
            float acc[4][4] = {};
            for (int kt = 0; kt < 64; kt++) {
                int kc = kt >> 4;
                if ((kt & 15) == 0) {
                    if (kc & 1) { MBAR_WAIT(mb1, (uint32_t)(ph1 & 1)); ph1++; }
                    else        { MBAR_WAIT(mb0, (uint32_t)(ph0 & 1)); ph0++; }
                }
                uint4 ahn;
                if (kt < 63)
                    ahn = *(const uint4*)(Ag + ((size_t)((kt + 1) * 4 + mt) << 9) + lane * 16);
                const unsigned char* bb = sm + (kc & 1) * 65536 + gsel + ((kt & 15) << 11) + (nh << 10);
                uint2 bh[4];
#pragma unroll
                for (int j = 0; j < 4; j++)
                    bh[j] = *(const uint2*)(bb + (j << 8) + lane * 8);
#pragma unroll
                for (int j = 0; j < 4; j++) MMAH(acc[j], ahc, bh[j]);
                if ((kt & 15) == 15 && kc < 2) {
                    __syncthreads();
                    if (tid == 0) {
                        uint32_t mbk = (kc & 1) ? mb1 : mb0;
                        uint32_t slot = smem_u32(sm + (kc & 1) * 65536);
                        MBAR_EXPECT(mbk, 65536);
                        bulk_g2s(slot, Bi0 + (kc + 2) * 32768, 32768, mbk);
                        bulk_g2s(slot + 32768, Bi1 + (kc + 2) * 32768, 32768, mbk);
                    }
                }
                ahc = ahn;
            }
            __syncthreads();
            // ---------------- epilogue L1 ----------------
            float s0 = 0.f, q0 = 0.f, s1 = 0.f, q1 = 0.f;
            int r0 = g * 64 + mt * 16 + (lane >> 2);
#pragma unroll
            for (int j = 0; j < 4; j++) {
                int cl = (nh * 4 + j) * 8 + (lane & 3) * 2;
                Cs[r0][cl] = acc[j][0]; Cs[r0][cl + 1] = acc[j][1];
                Cs[r0 + 8][cl] = acc[j][2]; Cs[r0 + 8][cl + 1] = acc[j][3];
                s0 += acc[j][0] + acc[j][1];
                q0 += acc[j][0] * acc[j][0] + acc[j][1] * acc[j][1];
                s1 += acc[j][2] + acc[j][3];
                q1 += acc[j][2] * acc[j][2] + acc[j][3] * acc[j][3];
            }
            s0 += __shfl_xor_sync(0xffffffffu, s0, 1); s0 += __shfl_xor_sync(0xffffffffu, s0, 2);
            q0 += __shfl_xor_sync(0xffffffffu, q0, 1); q0 += __shfl_xor_sync(0xffffffffu, q0, 2);
            s1 += __shfl_xor_sync(0xffffffffu, s1, 1); s1 += __shfl_xor_sync(0xffffffffu, s1, 2);
            q1 += __shfl_xor_sync(0xffffffffu, q1, 1); q1 += __shfl_xor_sync(0xffffffffu, q1, 2);
            if ((lane & 3) == 0) {
                prS[r0 * 2 + nh] = s0; pqS[r0 * 2 + nh] = q0;
                prS[(r0 + 8) * 2 + nh] = s1; pqS[(r0 + 8) * 2 + nh] = q1;
            }
            __syncthreads();
            if (tid < 128) {
                float s = prS[tid * 2] + prS[tid * 2 + 1];
                float q = pqS[tid * 2] + pqS[tid * 2 + 1];
                float m = s * (1.f / 64.f);
                float var = fmaxf(q * (1.f / 64.f) - m * m, 0.f);
                int rr_ = tid & 63;
                int gi = (rr_ >> 4) * Hn + c * 16 + (rr_ & 15);
                float gam = (tid < 64) ? gx1[gi] : gh1[gi];
                mS[tid] = m; sS[tid] = gam * rsqrtf(var + 1e-5f);
            }
            __syncthreads();
            int hcl = tid & 15, bg = tid >> 4;
            int hc = c * 16 + hcl;
            float ov[2], ps = 0.f, p2 = 0.f;
            float bI = b1[hc], bJ = b1[Hn + hc], bF = b1[2 * Hn + hc], bO = b1[3 * Hn + hc];
#pragma unroll
            for (int i = 0; i < 2; i++) {
                int b_ = bg * 2 + i;
                float preI = (Cs[hcl][b_] - mS[hcl]) * sS[hcl]
                           + (Cs[64 + hcl][b_] - mS[64 + hcl]) * sS[64 + hcl] + bI;
                float preJ = (Cs[16 + hcl][b_] - mS[16 + hcl]) * sS[16 + hcl]
                           + (Cs[80 + hcl][b_] - mS[80 + hcl]) * sS[80 + hcl] + bJ;
                float preF = (Cs[32 + hcl][b_] - mS[32 + hcl]) * sS[32 + hcl]
                           + (Cs[96 + hcl][b_] - mS[96 + hcl]) * sS[96 + hcl] + bF;
                float preO = (Cs[48 + hcl][b_] - mS[48 + hcl]) * sS[48 + hcl]
                           + (Cs[112 + hcl][b_] - mS[112 + hcl]) * sS[112 + hcl] + bO;
                float cn = sigm(preF + 1.f) * creg[i] + sigm(preI) * tanhf(preJ);
                creg[i] = cn; ov[i] = preO; ps += cn; p2 += cn * cn;
            }
            psA[bg * 16 + hcl] = ps; ps2A[bg * 16 + hcl] = p2;
            __syncthreads();
            if (tid < 16) {
                float s = 0.f, s2 = 0.f;
#pragma unroll
                for (int gg = 0; gg < 32; gg++) { s += psA[gg * 16 + tid]; s2 += ps2A[gg * 16 + tid]; }
                float m = s * (1.f / 64.f);
                float var = fmaxf(s2 * (1.f / 64.f) - m * m, 0.f);
                mcA[tid] = m; rsA[tid] = rsqrtf(var + 1e-5f);
            }
            __syncthreads();
            float gcv = gc1[hc], bcv = bc1[hc], mm = mcA[hcl], rr = rsA[hcl];
            unsigned char* hb = g_h1B[(u + 1) & 1];
#pragma unroll
            for (int i = 0; i < 2; i++) {
                int b_ = bg * 2 + i;
                float cn = gcv * (creg[i] - mm) * rr + bcv;
                float h = sigm(ov[i]) * tanhf(cn);
                write_hfrag(hb, b_, hc, h);
                __nv_bfloat16 hhi = __float2bfloat16(h);
                __nv_bfloat16 hlo = __float2bfloat16(h - __bfloat162float(hhi));
                size_t off = afrag_off1k(b_ * Tn + u, hc);
                *(__nv_bfloat16*)(g_Hf + off) = hhi;
                *(__nv_bfloat16*)(g_Hf + HPLANE + off) = hlo;
            }
        }
        grid_bar();
    }
}

// ------------------------------ launch ------------------------------------
extern "C" void kernel_launch(void* const* d_in, const int* in_sizes, int n_in,
                              void* d_out, int out_size) {
    const int*   inp = (const int*)  d_in[0];
    const float* emb = (const float*)d_in[1];
    const float* Wx0 = (const float*)d_in[2];
    const float* Wh0 = (const float*)d_in[3];
    const float* b0  = (const float*)d_in[4];
    const float* gx0 = (const float*)d_in[5];
    const float* gh0 = (const float*)d_in[6];
    const float* gc0 = (const float*)d_in[7];
    const float* bc0 = (const float*)d_in[8];
    const float* Wx1 = (const float*)d_in[9];
    const float* Wh1 = (const float*)d_in[10];
    const float* b1  = (const float*)d_in[11];
    const float* gx1 = (const float*)d_in[12];
    const float* gh1 = (const float*)d_in[13];
    const float* gc1 = (const float*)d_in[14];
    const float* bc1 = (const float*)d_in[15];
    const float* Wp  = (const float*)d_in[16];
    const float* bp  = (const float*)d_in[17];
    const float* sw  = (const float*)d_in[18];
    const float* sb  = (const float*)d_in[19];
    float* out = (float*)d_out;

    unsigned char *pXf, *pWx0B;
    cudaGetSymbolAddress((void**)&pXf,  g_Xf);
    cudaGetSymbolAddress((void**)&pWx0B, g_Wx0B);

    cudaFuncSetAttribute(k_scan, cudaFuncAttributeMaxDynamicSharedMemorySize, 138496);
    cudaFuncSetAttribute(k_gemm_gx0, cudaFuncAttributeMaxDynamicSharedMemorySize, 65536);
    cudaFuncSetAttribute(k_gemm_wp, cudaFuncAttributeMaxDynamicSharedMemorySize, 131072);
    cudaFuncSetAttribute(k_gemm_logits, cudaFuncAttributeMaxDynamicSharedMemorySize, 32768);

    k_embed<<<Tn * Bn, 256>>>(inp, emb);
    k_prepw<<<dim3(16384, 3), 256>>>(Wh0, Wx1, Wh1);
    k_prepB<<<(NUn * (FH + Vn)) / 256, 256>>>(Wx0, sw);
    k_prepWp<<<(Hn * NUn) / 256, 256>>>(Wp);
    k_gemm_gx0<<<dim3(FH / 64, 64), 256, 65536>>>(pXf, pWx0B, gx0);
    k_scan<<<NBLK, 512, 138496>>>(b0, gh0, gc0, bc0, b1, gx1, gh1, gc1, bc1);
    k_gemm_wp<<<dim3(NUn / 64, 64), 256, 131072>>>(bp);
    k_gemm_logits<<<dim3(Vn / 64, 64), 256, 32768>>>(sb, out);
}